// round 1
// baseline (speedup 1.0000x reference)
#include <cuda_runtime.h>
#include <math.h>

#define LL 24
#define NN 8192
#define DIN 256
#define DOUT 128
#define NWX 512     // 4*DOUT
#define NU  640     // 5*DOUT (f1,f2,i,u,o interleaved per d)

// Scratch: W_x for all levels (computed once, no recurrent dependency). 402 MB.
__device__ float g_Wx[(size_t)LL * NN * NWX];
// Permuted recurrent weight matrix, layout [k][j] with j = d*5 + which.
__device__ float g_Uperm[DIN * NU];

__device__ __forceinline__ float sigmoidf_(float x) {
    return 1.0f / (1.0f + __expf(-x));
}

// Build permuted U: column j = d*5 + w; w: 0=f1, 1=f2, 2=i, 3=u, 4=o.
__global__ void build_uperm(const float* __restrict__ Uf1,
                            const float* __restrict__ Uf2,
                            const float* __restrict__ Uiuo) {
    int t = blockIdx.x * blockDim.x + threadIdx.x;
    if (t >= DIN * NU) return;
    int k = t / NU;
    int j = t % NU;
    int d = j / 5;
    int w = j % 5;
    float v;
    if (w == 0)      v = Uf1[d * DIN + k];
    else if (w == 1) v = Uf2[d * DIN + k];
    else             v = Uiuo[((w - 2) * DOUT + d) * DIN + k];
    g_Uperm[(size_t)k * NU + j] = v;
}

// W_x = X @ W_w.T + W_b for all L*N rows. M=196608, N=512, K=256.
// BM=64, BN=64, BK=32, 256 threads, 4x4 per thread.
__global__ __launch_bounds__(256) void pre_gemm(const float* __restrict__ X,
                                                const float* __restrict__ Ww,
                                                const float* __restrict__ Wb) {
    __shared__ float As[32][65];
    __shared__ float Bs[32][65];
    int bm = blockIdx.x * 64;
    int bn = blockIdx.y * 64;
    int tid = threadIdx.x;
    int tx = tid & 15, ty = tid >> 4;
    int ka = tid & 31, ra = tid >> 5;

    float acc[4][4];
#pragma unroll
    for (int i = 0; i < 4; i++)
#pragma unroll
        for (int j = 0; j < 4; j++) acc[i][j] = 0.f;

    for (int kt = 0; kt < DIN; kt += 32) {
#pragma unroll
        for (int i = 0; i < 8; i++) {
            int r = ra + i * 8;
            As[ka][r] = X[(size_t)(bm + r) * DIN + kt + ka];
            Bs[ka][r] = Ww[(size_t)(bn + r) * DIN + kt + ka];
        }
        __syncthreads();
#pragma unroll
        for (int kk = 0; kk < 32; kk++) {
            float a[4], b[4];
#pragma unroll
            for (int i = 0; i < 4; i++) a[i] = As[kk][ty * 4 + i];
#pragma unroll
            for (int j = 0; j < 4; j++) b[j] = Bs[kk][tx * 4 + j];
#pragma unroll
            for (int i = 0; i < 4; i++)
#pragma unroll
                for (int j = 0; j < 4; j++) acc[i][j] = fmaf(a[i], b[j], acc[i][j]);
        }
        __syncthreads();
    }
#pragma unroll
    for (int i = 0; i < 4; i++) {
        size_t row = (size_t)(bm + ty * 4 + i) * NWX;
#pragma unroll
        for (int j = 0; j < 4; j++) {
            int col = bn + tx * 4 + j;
            g_Wx[row + col] = acc[i][j] + Wb[col];
        }
    }
}

// One recurrent level, fully fused: gather child h (from prev level's output
// slice) -> GEMM [8192 x 640] = hc @ Uperm -> LSTM gate epilogue -> write
// res_h / res_c directly into d_out.
// Grid: (NN/64, DOUT/16). Block 256 threads. Thread: 4 rows x 1 d-group(5 cols).
__global__ __launch_bounds__(256) void level_kernel(
    int lvl,
    const int* __restrict__ indices,
    const float* __restrict__ hInit,
    const float* __restrict__ cInit,
    float* __restrict__ outH,
    float* __restrict__ outC)
{
    __shared__ float As[32][65];
    __shared__ float Bs[32][81];
    __shared__ int sIdx[64][2];

    int bm = blockIdx.x * 64;
    int dBase = blockIdx.y * 16;
    int tid = threadIdx.x;
    int tx = tid & 15, ty = tid >> 4;
    int ka = tid & 31, ra = tid >> 5;

    if (tid < 128) {
        int r = tid >> 1, c = tid & 1;
        sIdx[r][c] = indices[(size_t)lvl * NN * 2 + (size_t)(bm + r) * 2 + c];
    }
    __syncthreads();

    // At level 0, h_prev/c_prev are broadcast h_init/c_init, so every gather
    // (any idx) returns the init state.
    const float* prevH = (lvl == 0) ? nullptr : outH + (size_t)(lvl - 1) * NN * DOUT;
    const float* prevC = (lvl == 0) ? nullptr : outC + (size_t)(lvl - 1) * NN * DOUT;

    float acc[4][5];
#pragma unroll
    for (int i = 0; i < 4; i++)
#pragma unroll
        for (int w = 0; w < 5; w++) acc[i][w] = 0.f;

    for (int kt = 0; kt < DIN; kt += 32) {
        int half = (kt >= 128) ? 1 : 0;   // child 0 then child 1
        int kd = (kt & 127) + ka;         // dim within child's h vector
        // A tile: gathered hc[bm..bm+63][kt..kt+31]
#pragma unroll
        for (int i = 0; i < 8; i++) {
            int r = ra + i * 8;
            int ci = sIdx[r][half];
            float v;
            if (prevH != nullptr && ci >= 0) v = prevH[(size_t)ci * DOUT + kd];
            else                             v = hInit[kd];
            As[ka][r] = v;
        }
        // B tile: Uperm[kt..kt+31][dBase*5 .. dBase*5+79]
#pragma unroll
        for (int s = 0; s < 10; s++) {
            int e = tid + s * 256;
            int k = e / 80, j = e % 80;
            Bs[k][j] = g_Uperm[(size_t)(kt + k) * NU + dBase * 5 + j];
        }
        __syncthreads();
#pragma unroll
        for (int kk = 0; kk < 32; kk++) {
            float a[4], b[5];
#pragma unroll
            for (int i = 0; i < 4; i++) a[i] = As[kk][ty * 4 + i];
#pragma unroll
            for (int w = 0; w < 5; w++) b[w] = Bs[kk][tx * 5 + w];
#pragma unroll
            for (int i = 0; i < 4; i++)
#pragma unroll
                for (int w = 0; w < 5; w++) acc[i][w] = fmaf(a[i], b[w], acc[i][w]);
        }
        __syncthreads();
    }

    // Fused LSTM gate epilogue.
    int d = dBase + tx;
#pragma unroll
    for (int i = 0; i < 4; i++) {
        int rl = ty * 4 + i;
        int n = bm + rl;
        const float* wx = g_Wx + ((size_t)lvl * NN + n) * NWX;
        float f_x = wx[d];
        float i_x = wx[DOUT + d];
        float u_x = wx[2 * DOUT + d];
        float o_x = wx[3 * DOUT + d];

        float f1 = sigmoidf_(f_x + acc[i][0]);
        float f2 = sigmoidf_(f_x + acc[i][1]);
        float ig = sigmoidf_(acc[i][2] + i_x);
        float ug = tanhf(acc[i][3] + u_x);
        float og = sigmoidf_(acc[i][4] + o_x);

        int c0i = sIdx[rl][0], c1i = sIdx[rl][1];
        float c0 = (prevC != nullptr && c0i >= 0) ? prevC[(size_t)c0i * DOUT + d] : cInit[d];
        float c1 = (prevC != nullptr && c1i >= 0) ? prevC[(size_t)c1i * DOUT + d] : cInit[d];

        float nc = ig * ug + f1 * c0 + f2 * c1;
        float nh = og * tanhf(nc);

        size_t o = ((size_t)lvl * NN + n) * DOUT + d;
        outH[o] = nh;
        outC[o] = nc;
    }
}

extern "C" void kernel_launch(void* const* d_in, const int* in_sizes, int n_in,
                              void* d_out, int out_size) {
    const float* tensor = (const float*)d_in[0];   // [L, N, DIN]
    const int*   indices = (const int*)d_in[1];    // [L, N, 2]
    const float* h_init = (const float*)d_in[2];   // [1, DOUT]
    const float* c_init = (const float*)d_in[3];   // [1, DOUT]
    const float* W_w   = (const float*)d_in[4];    // [4*DOUT, DIN]
    const float* W_b   = (const float*)d_in[5];    // [4*DOUT]
    const float* U_f1  = (const float*)d_in[6];    // [DOUT, 2*DOUT]
    const float* U_f2  = (const float*)d_in[7];
    const float* U_iuo = (const float*)d_in[8];    // [3*DOUT, 2*DOUT]

    float* outH = (float*)d_out;                         // res_h [L,N,DOUT]
    float* outC = outH + (size_t)LL * NN * DOUT;         // res_c [L,N,DOUT]

    build_uperm<<<(DIN * NU + 255) / 256, 256>>>(U_f1, U_f2, U_iuo);

    dim3 pg(LL * NN / 64, NWX / 64);
    pre_gemm<<<pg, 256>>>(tensor, W_w, W_b);

    dim3 lg(NN / 64, DOUT / 16);
    for (int lvl = 0; lvl < LL; lvl++) {
        level_kernel<<<lg, 256>>>(lvl, indices, h_init, c_init, outH, outC);
    }
}

// round 2
// speedup vs baseline: 1.0036x; 1.0036x over previous
#include <cuda_runtime.h>
#include <math.h>

#define LL 24
#define NN 8192
#define DIN 256
#define DOUT 128
#define NWX 512     // 4*DOUT
#define NU  640     // 5*DOUT (f1,f2,i,u,o interleaved per d)

// Scratch: W_x for all levels (computed once, no recurrent dependency). 402 MB.
__device__ float g_Wx[(size_t)LL * NN * NWX];
// Permuted recurrent weight matrix, layout [k][j] with j = d*5 + which.
__device__ float g_Uperm[DIN * NU];

__device__ __forceinline__ float sigmoidf_(float x) {
    return 1.0f / (1.0f + __expf(-x));
}

// Build permuted U: column j = d*5 + w; w: 0=f1, 1=f2, 2=i, 3=u, 4=o.
__global__ void build_uperm(const float* __restrict__ Uf1,
                            const float* __restrict__ Uf2,
                            const float* __restrict__ Uiuo) {
    int t = blockIdx.x * blockDim.x + threadIdx.x;
    if (t >= DIN * NU) return;
    int k = t / NU;
    int j = t % NU;
    int d = j / 5;
    int w = j % 5;
    float v;
    if (w == 0)      v = Uf1[d * DIN + k];
    else if (w == 1) v = Uf2[d * DIN + k];
    else             v = Uiuo[((w - 2) * DOUT + d) * DIN + k];
    g_Uperm[(size_t)k * NU + j] = v;
}

// W_x = X @ W_w.T + W_b for all L*N rows. M=196608, N=512, K=256.
// BM=64, BN=64, BK=32, 256 threads, 4x4 per thread.
__global__ __launch_bounds__(256) void pre_gemm(const float* __restrict__ X,
                                                const float* __restrict__ Ww,
                                                const float* __restrict__ Wb) {
    __shared__ float As[32][65];
    __shared__ float Bs[32][65];
    int bm = blockIdx.x * 64;
    int bn = blockIdx.y * 64;
    int tid = threadIdx.x;
    int tx = tid & 15, ty = tid >> 4;
    int ka = tid & 31, ra = tid >> 5;

    float acc[4][4];
#pragma unroll
    for (int i = 0; i < 4; i++)
#pragma unroll
        for (int j = 0; j < 4; j++) acc[i][j] = 0.f;

    for (int kt = 0; kt < DIN; kt += 32) {
#pragma unroll
        for (int i = 0; i < 8; i++) {
            int r = ra + i * 8;
            As[ka][r] = X[(size_t)(bm + r) * DIN + kt + ka];
            Bs[ka][r] = Ww[(size_t)(bn + r) * DIN + kt + ka];
        }
        __syncthreads();
#pragma unroll
        for (int kk = 0; kk < 32; kk++) {
            float a[4], b[4];
#pragma unroll
            for (int i = 0; i < 4; i++) a[i] = As[kk][ty * 4 + i];
#pragma unroll
            for (int j = 0; j < 4; j++) b[j] = Bs[kk][tx * 4 + j];
#pragma unroll
            for (int i = 0; i < 4; i++)
#pragma unroll
                for (int j = 0; j < 4; j++) acc[i][j] = fmaf(a[i], b[j], acc[i][j]);
        }
        __syncthreads();
    }
#pragma unroll
    for (int i = 0; i < 4; i++) {
        size_t row = (size_t)(bm + ty * 4 + i) * NWX;
#pragma unroll
        for (int j = 0; j < 4; j++) {
            int col = bn + tx * 4 + j;
            g_Wx[row + col] = acc[i][j] + Wb[col];
        }
    }
}

// One recurrent level, fully fused: gather child h (from prev level's output
// slice) -> GEMM [8192 x 640] = hc @ Uperm -> LSTM gate epilogue -> write
// res_h / res_c directly into d_out.
// Grid: (NN/64, DOUT/16). Block 256 threads. Thread: 4 rows x 1 d-group(5 cols).
__global__ __launch_bounds__(256) void level_kernel(
    int lvl,
    const int* __restrict__ indices,
    const float* __restrict__ hInit,
    const float* __restrict__ cInit,
    float* __restrict__ outH,
    float* __restrict__ outC)
{
    __shared__ float As[32][65];
    __shared__ float Bs[32][81];
    __shared__ int sIdx[64][2];

    int bm = blockIdx.x * 64;
    int dBase = blockIdx.y * 16;
    int tid = threadIdx.x;
    int tx = tid & 15, ty = tid >> 4;
    int ka = tid & 31, ra = tid >> 5;

    if (tid < 128) {
        int r = tid >> 1, c = tid & 1;
        sIdx[r][c] = indices[(size_t)lvl * NN * 2 + (size_t)(bm + r) * 2 + c];
    }
    __syncthreads();

    // At level 0, h_prev/c_prev are broadcast h_init/c_init, so every gather
    // (any idx) returns the init state.
    const float* prevH = (lvl == 0) ? nullptr : outH + (size_t)(lvl - 1) * NN * DOUT;
    const float* prevC = (lvl == 0) ? nullptr : outC + (size_t)(lvl - 1) * NN * DOUT;

    float acc[4][5];
#pragma unroll
    for (int i = 0; i < 4; i++)
#pragma unroll
        for (int w = 0; w < 5; w++) acc[i][w] = 0.f;

    for (int kt = 0; kt < DIN; kt += 32) {
        int half = (kt >= 128) ? 1 : 0;   // child 0 then child 1
        int kd = (kt & 127) + ka;         // dim within child's h vector
        // A tile: gathered hc[bm..bm+63][kt..kt+31]
#pragma unroll
        for (int i = 0; i < 8; i++) {
            int r = ra + i * 8;
            int ci = sIdx[r][half];
            float v;
            if (prevH != nullptr && ci >= 0) v = prevH[(size_t)ci * DOUT + kd];
            else                             v = hInit[kd];
            As[ka][r] = v;
        }
        // B tile: Uperm[kt..kt+31][dBase*5 .. dBase*5+79]
#pragma unroll
        for (int s = 0; s < 10; s++) {
            int e = tid + s * 256;
            int k = e / 80, j = e % 80;
            Bs[k][j] = g_Uperm[(size_t)(kt + k) * NU + dBase * 5 + j];
        }
        __syncthreads();
#pragma unroll
        for (int kk = 0; kk < 32; kk++) {
            float a[4], b[5];
#pragma unroll
            for (int i = 0; i < 4; i++) a[i] = As[kk][ty * 4 + i];
#pragma unroll
            for (int w = 0; w < 5; w++) b[w] = Bs[kk][tx * 5 + w];
#pragma unroll
            for (int i = 0; i < 4; i++)
#pragma unroll
                for (int w = 0; w < 5; w++) acc[i][w] = fmaf(a[i], b[w], acc[i][w]);
        }
        __syncthreads();
    }

    // Fused LSTM gate epilogue.
    int d = dBase + tx;
#pragma unroll
    for (int i = 0; i < 4; i++) {
        int rl = ty * 4 + i;
        int n = bm + rl;
        const float* wx = g_Wx + ((size_t)lvl * NN + n) * NWX;
        float f_x = wx[d];
        float i_x = wx[DOUT + d];
        float u_x = wx[2 * DOUT + d];
        float o_x = wx[3 * DOUT + d];

        float f1 = sigmoidf_(f_x + acc[i][0]);
        float f2 = sigmoidf_(f_x + acc[i][1]);
        float ig = sigmoidf_(acc[i][2] + i_x);
        float ug = tanhf(acc[i][3] + u_x);
        float og = sigmoidf_(acc[i][4] + o_x);

        int c0i = sIdx[rl][0], c1i = sIdx[rl][1];
        float c0 = (prevC != nullptr && c0i >= 0) ? prevC[(size_t)c0i * DOUT + d] : cInit[d];
        float c1 = (prevC != nullptr && c1i >= 0) ? prevC[(size_t)c1i * DOUT + d] : cInit[d];

        float nc = ig * ug + f1 * c0 + f2 * c1;
        float nh = og * tanhf(nc);

        size_t o = ((size_t)lvl * NN + n) * DOUT + d;
        outH[o] = nh;
        outC[o] = nc;
    }
}

extern "C" void kernel_launch(void* const* d_in, const int* in_sizes, int n_in,
                              void* d_out, int out_size) {
    const float* tensor = (const float*)d_in[0];   // [L, N, DIN]
    const int*   indices = (const int*)d_in[1];    // [L, N, 2]
    const float* h_init = (const float*)d_in[2];   // [1, DOUT]
    const float* c_init = (const float*)d_in[3];   // [1, DOUT]
    const float* W_w   = (const float*)d_in[4];    // [4*DOUT, DIN]
    const float* W_b   = (const float*)d_in[5];    // [4*DOUT]
    const float* U_f1  = (const float*)d_in[6];    // [DOUT, 2*DOUT]
    const float* U_f2  = (const float*)d_in[7];
    const float* U_iuo = (const float*)d_in[8];    // [3*DOUT, 2*DOUT]

    float* outH = (float*)d_out;                         // res_h [L,N,DOUT]
    float* outC = outH + (size_t)LL * NN * DOUT;         // res_c [L,N,DOUT]

    build_uperm<<<(DIN * NU + 255) / 256, 256>>>(U_f1, U_f2, U_iuo);

    dim3 pg(LL * NN / 64, NWX / 64);
    pre_gemm<<<pg, 256>>>(tensor, W_w, W_b);

    dim3 lg(NN / 64, DOUT / 16);
    for (int lvl = 0; lvl < LL; lvl++) {
        level_kernel<<<lg, 256>>>(lvl, indices, h_init, c_init, outH, outC);
    }
}

// round 3
// speedup vs baseline: 1.2458x; 1.2414x over previous
#include <cuda_runtime.h>
#include <math.h>

#define LL 24
#define NN 8192
#define DIN 256
#define DOUT 128
#define NWX 512     // 4*DOUT
#define NU  640     // 5*DOUT

// Scratch: W_x for all levels, permuted layout [lvl][n][d][gate], gate=(f,i,u,o). 402 MB.
__device__ float g_Wx[(size_t)LL * NN * NWX];
// Permuted recurrent weights, [k][j] with j = d*5 + w; w: 0=f1,1=f2,2=i,3=u,4=o.
__device__ float g_Uperm[DIN * NU];

__device__ __forceinline__ float sigmoidf_(float x) {
    return 1.0f / (1.0f + __expf(-x));
}

__global__ void build_uperm(const float* __restrict__ Uf1,
                            const float* __restrict__ Uf2,
                            const float* __restrict__ Uiuo) {
    int t = blockIdx.x * blockDim.x + threadIdx.x;
    if (t >= DIN * NU) return;
    int k = t / NU;
    int j = t % NU;
    int d = j / 5;
    int w = j % 5;
    float v;
    if (w == 0)      v = Uf1[d * DIN + k];
    else if (w == 1) v = Uf2[d * DIN + k];
    else             v = Uiuo[((w - 2) * DOUT + d) * DIN + k];
    g_Uperm[(size_t)k * NU + j] = v;
}

// ---------------------------------------------------------------------------
// pre_gemm: W_x = X @ Ww.T + Wb for all L*N rows, written in permuted layout.
// M=196608, N=512(permuted cols c=d*4+g), K=256. BM=128,BN=128,BK=16.
// 256 threads, 8x8 per thread with stride-16 mapping. Double-buffered.
// ---------------------------------------------------------------------------
__global__ __launch_bounds__(256, 2) void pre_gemm(const float* __restrict__ X,
                                                   const float* __restrict__ Ww,
                                                   const float* __restrict__ Wb) {
    __shared__ float As[2][128][17];
    __shared__ float Bs[2][128][17];

    int bm = blockIdx.y * 128;
    int bn = blockIdx.x * 128;          // permuted col base
    int tid = threadIdx.x;
    int tx = tid & 15, ty = tid >> 4;
    int kq = (tid & 3) * 4;             // k offset within tile: 0,4,8,12
    int rq = tid >> 2;                  // 0..63

    // permuted col c -> original Ww row: (c&3)*128 + (c>>2)
    int browMap[2];
#pragma unroll
    for (int i = 0; i < 2; i++) {
        int c = bn + rq + i * 64;
        browMap[i] = ((c & 3) << 7) + (c >> 2);
    }

    float acc[8][8];
#pragma unroll
    for (int i = 0; i < 8; i++)
#pragma unroll
        for (int j = 0; j < 8; j++) acc[i][j] = 0.f;

    float4 aS[2], bS[2];

    // prologue: tile 0
#pragma unroll
    for (int i = 0; i < 2; i++) {
        aS[i] = *(const float4*)&X[(size_t)(bm + rq + i * 64) * DIN + kq];
        bS[i] = *(const float4*)&Ww[(size_t)browMap[i] * DIN + kq];
    }
#pragma unroll
    for (int i = 0; i < 2; i++) {
        int m = rq + i * 64;
        As[0][m][kq + 0] = aS[i].x; As[0][m][kq + 1] = aS[i].y;
        As[0][m][kq + 2] = aS[i].z; As[0][m][kq + 3] = aS[i].w;
        Bs[0][m][kq + 0] = bS[i].x; Bs[0][m][kq + 1] = bS[i].y;
        Bs[0][m][kq + 2] = bS[i].z; Bs[0][m][kq + 3] = bS[i].w;
    }
    __syncthreads();

    int buf = 0;
    for (int t = 0; t < 16; t++) {
        if (t < 15) {
            int kt = (t + 1) * 16;
#pragma unroll
            for (int i = 0; i < 2; i++) {
                aS[i] = *(const float4*)&X[(size_t)(bm + rq + i * 64) * DIN + kt + kq];
                bS[i] = *(const float4*)&Ww[(size_t)browMap[i] * DIN + kt + kq];
            }
        }
#pragma unroll
        for (int kk = 0; kk < 16; kk++) {
            float a[8], b[8];
#pragma unroll
            for (int i = 0; i < 8; i++) a[i] = As[buf][ty + i * 16][kk];
#pragma unroll
            for (int j = 0; j < 8; j++) b[j] = Bs[buf][tx + j * 16][kk];
#pragma unroll
            for (int i = 0; i < 8; i++)
#pragma unroll
                for (int j = 0; j < 8; j++) acc[i][j] = fmaf(a[i], b[j], acc[i][j]);
        }
        if (t < 15) {
            int nb = buf ^ 1;
#pragma unroll
            for (int i = 0; i < 2; i++) {
                int m = rq + i * 64;
                As[nb][m][kq + 0] = aS[i].x; As[nb][m][kq + 1] = aS[i].y;
                As[nb][m][kq + 2] = aS[i].z; As[nb][m][kq + 3] = aS[i].w;
                Bs[nb][m][kq + 0] = bS[i].x; Bs[nb][m][kq + 1] = bS[i].y;
                Bs[nb][m][kq + 2] = bS[i].z; Bs[nb][m][kq + 3] = bS[i].w;
            }
        }
        __syncthreads();
        buf ^= 1;
    }

    float wb[8];
#pragma unroll
    for (int j = 0; j < 8; j++) {
        int c = bn + tx + j * 16;
        wb[j] = Wb[((c & 3) << 7) + (c >> 2)];
    }
#pragma unroll
    for (int i = 0; i < 8; i++) {
        size_t row = (size_t)(bm + ty + i * 16) * NWX;
#pragma unroll
        for (int j = 0; j < 8; j++) {
            g_Wx[row + bn + tx + j * 16] = acc[i][j] + wb[j];
        }
    }
}

// ---------------------------------------------------------------------------
// level_kernel: gather child h -> [8192 x 640] GEMM vs Uperm -> fused gates.
// BM=128, BN=80 (16 d-groups * 5), BK=16, 256 threads, 8x5 per thread.
// Double-buffered with register staging. Grid (8, 64): d-group fastest.
// ---------------------------------------------------------------------------
__global__ __launch_bounds__(256, 2) void level_kernel(
    int lvl,
    const int* __restrict__ indices,
    const float* __restrict__ hInit,
    const float* __restrict__ cInit,
    float* __restrict__ outH,
    float* __restrict__ outC)
{
    __shared__ float As[2][128][17];
    __shared__ float Bs[2][80][17];
    __shared__ int sIdx[128][2];
    __shared__ float sInitH[128];
    __shared__ float sInitC[128];

    int grp = blockIdx.x;               // d-group block: dBase = grp*16
    int bm = blockIdx.y * 128;
    int tid = threadIdx.x;
    int tx = tid & 15, ty = tid >> 4;
    int lka = tid & 15;                 // loader: k within tile
    int lra = tid >> 4;                 // loader: row group 0..15

    if (tid < 128) { sInitH[tid] = hInit[tid]; sInitC[tid] = cInit[tid]; }
    {
        int r = tid >> 1, c = tid & 1;
        sIdx[r][c] = indices[(size_t)lvl * NN * 2 + (size_t)(bm + r) * 2 + c];
    }
    __syncthreads();

    bool hasPrev = (lvl != 0);
    const float* prevH = outH + (size_t)(lvl - 1) * NN * DOUT;   // only read if hasPrev
    const float* prevC = outC + (size_t)(lvl - 1) * NN * DOUT;

    float acc[8][5];
#pragma unroll
    for (int i = 0; i < 8; i++)
#pragma unroll
        for (int w = 0; w < 5; w++) acc[i][w] = 0.f;

    float aReg[8], bReg[5];
    int colBase = grp * 80;

    // ---- prologue: tile 0 ----
    {
        int kt = 0;
        int half = 0;
        int kd = kt + lka;
#pragma unroll
        for (int i = 0; i < 8; i++) {
            int r = lra + i * 16;
            int ci = sIdx[r][half];
            aReg[i] = (hasPrev && ci >= 0) ? prevH[(size_t)ci * DOUT + kd] : sInitH[kd];
        }
#pragma unroll
        for (int s = 0; s < 5; s++) {
            int e = tid + s * 256;
            int bk = e / 80, bj = e - bk * 80;
            bReg[s] = g_Uperm[(size_t)bk * NU + colBase + bj];
        }
#pragma unroll
        for (int i = 0; i < 8; i++) As[0][lra + i * 16][lka] = aReg[i];
#pragma unroll
        for (int s = 0; s < 5; s++) {
            int e = tid + s * 256;
            int bk = e / 80, bj = e - bk * 80;
            Bs[0][bj][bk] = bReg[s];
        }
    }
    __syncthreads();

    int buf = 0;
    for (int t = 0; t < 16; t++) {
        if (t < 15) {
            int kt = (t + 1) * 16;
            int half = (kt >= 128) ? 1 : 0;
            int kd = (kt & 127) + lka;
#pragma unroll
            for (int i = 0; i < 8; i++) {
                int r = lra + i * 16;
                int ci = sIdx[r][half];
                aReg[i] = (hasPrev && ci >= 0) ? prevH[(size_t)ci * DOUT + kd] : sInitH[kd];
            }
#pragma unroll
            for (int s = 0; s < 5; s++) {
                int e = tid + s * 256;
                int bk = e / 80, bj = e - bk * 80;
                bReg[s] = g_Uperm[(size_t)(kt + bk) * NU + colBase + bj];
            }
        }
#pragma unroll
        for (int kk = 0; kk < 16; kk++) {
            float a[8], b[5];
#pragma unroll
            for (int i = 0; i < 8; i++) a[i] = As[buf][ty + i * 16][kk];
#pragma unroll
            for (int w = 0; w < 5; w++) b[w] = Bs[buf][tx * 5 + w][kk];
#pragma unroll
            for (int i = 0; i < 8; i++)
#pragma unroll
                for (int w = 0; w < 5; w++) acc[i][w] = fmaf(a[i], b[w], acc[i][w]);
        }
        if (t < 15) {
            int nb = buf ^ 1;
#pragma unroll
            for (int i = 0; i < 8; i++) As[nb][lra + i * 16][lka] = aReg[i];
#pragma unroll
            for (int s = 0; s < 5; s++) {
                int e = tid + s * 256;
                int bk = e / 80, bj = e - bk * 80;
                Bs[nb][bj][bk] = bReg[s];
            }
        }
        __syncthreads();
        buf ^= 1;
    }

    // ---- fused LSTM gate epilogue ----
    int d = grp * 16 + tx;
#pragma unroll
    for (int i = 0; i < 8; i++) {
        int rl = ty + i * 16;
        int n = bm + rl;
        const float4 wv = *(const float4*)&g_Wx[(((size_t)lvl * NN + n) << 9) + (d << 2)];
        // wv: x=f_x, y=i_x, z=u_x, w=o_x
        float f1 = sigmoidf_(wv.x + acc[i][0]);
        float f2 = sigmoidf_(wv.x + acc[i][1]);
        float ig = sigmoidf_(wv.y + acc[i][2]);
        float ug = tanhf(wv.z + acc[i][3]);
        float og = sigmoidf_(wv.w + acc[i][4]);

        int c0i = sIdx[rl][0], c1i = sIdx[rl][1];
        float c0 = (hasPrev && c0i >= 0) ? prevC[(size_t)c0i * DOUT + d] : sInitC[d];
        float c1 = (hasPrev && c1i >= 0) ? prevC[(size_t)c1i * DOUT + d] : sInitC[d];

        float nc = ig * ug + f1 * c0 + f2 * c1;
        float nh = og * tanhf(nc);

        size_t o = ((size_t)lvl * NN + n) * DOUT + d;
        outH[o] = nh;
        outC[o] = nc;
    }
}

extern "C" void kernel_launch(void* const* d_in, const int* in_sizes, int n_in,
                              void* d_out, int out_size) {
    const float* tensor = (const float*)d_in[0];   // [L, N, DIN]
    const int*   indices = (const int*)d_in[1];    // [L, N, 2]
    const float* h_init = (const float*)d_in[2];   // [1, DOUT]
    const float* c_init = (const float*)d_in[3];   // [1, DOUT]
    const float* W_w   = (const float*)d_in[4];    // [4*DOUT, DIN]
    const float* W_b   = (const float*)d_in[5];    // [4*DOUT]
    const float* U_f1  = (const float*)d_in[6];    // [DOUT, 2*DOUT]
    const float* U_f2  = (const float*)d_in[7];
    const float* U_iuo = (const float*)d_in[8];    // [3*DOUT, 2*DOUT]

    float* outH = (float*)d_out;                         // res_h [L,N,DOUT]
    float* outC = outH + (size_t)LL * NN * DOUT;         // res_c [L,N,DOUT]

    build_uperm<<<(DIN * NU + 255) / 256, 256>>>(U_f1, U_f2, U_iuo);

    dim3 pg(NWX / 128, LL * NN / 128);                   // (4, 1536)
    pre_gemm<<<pg, 256>>>(tensor, W_w, W_b);

    dim3 lg(DOUT / 16, NN / 128);                        // (8, 64)
    for (int lvl = 0; lvl < LL; lvl++) {
        level_kernel<<<lg, 256>>>(lvl, indices, h_init, c_init, outH, outC);
    }
}

// round 4
// speedup vs baseline: 1.4462x; 1.1608x over previous
#include <cuda_runtime.h>
#include <math.h>

#define LL 24
#define NN 8192
#define DIN 256
#define DOUT 128
#define NWX 512     // 4*DOUT
#define NU  640     // 5*DOUT

// Scratch: W_x for all levels, permuted layout [lvl][n][d][gate], gate=(f,i,u,o). 402 MB.
__device__ float g_Wx[(size_t)LL * NN * NWX];
// Permuted recurrent weights, column-major: [col][k], col = d*5 + w; w:0=f1,1=f2,2=i,3=u,4=o.
__device__ float g_Uperm[(size_t)NU * DIN];

__device__ __forceinline__ float sigmoidf_(float x) {
    return 1.0f / (1.0f + __expf(-x));
}

__device__ __forceinline__ float f4c(const float4 v, int j) {
    return j == 0 ? v.x : j == 1 ? v.y : j == 2 ? v.z : v.w;
}

__global__ void build_uperm(const float* __restrict__ Uf1,
                            const float* __restrict__ Uf2,
                            const float* __restrict__ Uiuo) {
    int t = blockIdx.x * blockDim.x + threadIdx.x;
    if (t >= NU * DIN) return;
    int j = t / DIN;       // col
    int k = t - j * DIN;
    int d = j / 5;
    int w = j - d * 5;
    float v;
    if (w == 0)      v = Uf1[d * DIN + k];
    else if (w == 1) v = Uf2[d * DIN + k];
    else             v = Uiuo[((w - 2) * DOUT + d) * DIN + k];
    g_Uperm[t] = v;
}

// ---------------------------------------------------------------------------
// pre_gemm: W_x = X @ Ww.T + Wb, permuted output cols c = d*4+g.
// M=196608, N=512, K=256. BM=128, BN=128, BK=16. 256 thr, 8x8/thread.
// Smem [BK][BM] both sides, float4 fragment reads, double buffered.
// ---------------------------------------------------------------------------
__global__ __launch_bounds__(256, 2) void pre_gemm(const float* __restrict__ X,
                                                   const float* __restrict__ Ww,
                                                   const float* __restrict__ Wb) {
    __shared__ float As[2][16][132];
    __shared__ float Bs[2][16][132];

    int bm = blockIdx.y * 128;
    int bn = blockIdx.x * 128;
    int tid = threadIdx.x;
    int tx = tid & 15, ty = tid >> 4;

    // loader: tasks u = tid, tid+256 ; m = u>>2 (0..127), c = u&3 (16B chunk of 16-k tile)
    int m0 = tid >> 2, c0 = tid & 3;
    int m1 = m0 + 64;
    // permuted col -> original Ww row
    int cg0 = bn + m0, cg1 = bn + m1;
    int brow0 = ((cg0 & 3) << 7) + (cg0 >> 2);
    int brow1 = ((cg1 & 3) << 7) + (cg1 >> 2);

    const float* Xa0 = X + (size_t)(bm + m0) * DIN + c0 * 4;
    const float* Xa1 = X + (size_t)(bm + m1) * DIN + c0 * 4;
    const float* Wb0 = Ww + (size_t)brow0 * DIN + c0 * 4;
    const float* Wb1 = Ww + (size_t)brow1 * DIN + c0 * 4;

    float acc[8][8];
#pragma unroll
    for (int i = 0; i < 8; i++)
#pragma unroll
        for (int j = 0; j < 8; j++) acc[i][j] = 0.f;

    float4 aS0, aS1, bS0, bS1;
    aS0 = *(const float4*)Xa0;  aS1 = *(const float4*)Xa1;
    bS0 = *(const float4*)Wb0;  bS1 = *(const float4*)Wb1;
#pragma unroll
    for (int j = 0; j < 4; j++) {
        As[0][c0 * 4 + j][m0] = f4c(aS0, j);
        As[0][c0 * 4 + j][m1] = f4c(aS1, j);
        Bs[0][c0 * 4 + j][m0] = f4c(bS0, j);
        Bs[0][c0 * 4 + j][m1] = f4c(bS1, j);
    }
    __syncthreads();

    int buf = 0;
    for (int t = 0; t < 16; t++) {
        if (t < 15) {
            int kt = (t + 1) * 16;
            aS0 = *(const float4*)(Xa0 + kt);
            aS1 = *(const float4*)(Xa1 + kt);
            bS0 = *(const float4*)(Wb0 + kt);
            bS1 = *(const float4*)(Wb1 + kt);
        }
#pragma unroll
        for (int kk = 0; kk < 16; kk++) {
            float4 a0 = *(const float4*)&As[buf][kk][ty * 4];
            float4 a1 = *(const float4*)&As[buf][kk][ty * 4 + 64];
            float4 b0 = *(const float4*)&Bs[buf][kk][tx * 4];
            float4 b1 = *(const float4*)&Bs[buf][kk][tx * 4 + 64];
            float a[8] = {a0.x, a0.y, a0.z, a0.w, a1.x, a1.y, a1.z, a1.w};
            float b[8] = {b0.x, b0.y, b0.z, b0.w, b1.x, b1.y, b1.z, b1.w};
#pragma unroll
            for (int i = 0; i < 8; i++)
#pragma unroll
                for (int j = 0; j < 8; j++) acc[i][j] = fmaf(a[i], b[j], acc[i][j]);
        }
        if (t < 15) {
            int nb = buf ^ 1;
#pragma unroll
            for (int j = 0; j < 4; j++) {
                As[nb][c0 * 4 + j][m0] = f4c(aS0, j);
                As[nb][c0 * 4 + j][m1] = f4c(aS1, j);
                Bs[nb][c0 * 4 + j][m0] = f4c(bS0, j);
                Bs[nb][c0 * 4 + j][m1] = f4c(bS1, j);
            }
        }
        __syncthreads();
        buf ^= 1;
    }

    // epilogue: bias + store, two float4 groups per row
    float wb0[4], wb1[4];
#pragma unroll
    for (int j = 0; j < 4; j++) {
        int ca = bn + tx * 4 + j;
        int cb = bn + 64 + tx * 4 + j;
        wb0[j] = Wb[((ca & 3) << 7) + (ca >> 2)];
        wb1[j] = Wb[((cb & 3) << 7) + (cb >> 2)];
    }
#pragma unroll
    for (int i = 0; i < 8; i++) {
        int m = (i < 4) ? (ty * 4 + i) : (64 + ty * 4 + i - 4);
        size_t row = (size_t)(bm + m) * NWX;
        float4 o0, o1;
        o0.x = acc[i][0] + wb0[0]; o0.y = acc[i][1] + wb0[1];
        o0.z = acc[i][2] + wb0[2]; o0.w = acc[i][3] + wb0[3];
        o1.x = acc[i][4] + wb1[0]; o1.y = acc[i][5] + wb1[1];
        o1.z = acc[i][6] + wb1[2]; o1.w = acc[i][7] + wb1[3];
        *(float4*)&g_Wx[row + bn + tx * 4] = o0;
        *(float4*)&g_Wx[row + bn + 64 + tx * 4] = o1;
    }
}

// ---------------------------------------------------------------------------
// level_kernel: gather child h -> [8192 x 640] GEMM -> fused LSTM gates.
// BM=128, BN=80, BK=16, 256 threads, 8x5/thread.
// As[BK][BM] (transpose-on-store from LDG.128 gather), Bs[BN][BK] (float4 k).
// ---------------------------------------------------------------------------
__global__ __launch_bounds__(256, 2) void level_kernel(
    int lvl,
    const int* __restrict__ indices,
    const float* __restrict__ hInit,
    const float* __restrict__ cInit,
    float* __restrict__ outH,
    float* __restrict__ outC)
{
    __shared__ float As[2][16][132];
    __shared__ float Bs[2][80][20];
    __shared__ int sIdx[128][2];
    __shared__ __align__(16) float sInitH[128];
    __shared__ __align__(16) float sInitC[128];

    int grp = blockIdx.x;                 // d-group block: dBase = grp*16
    int bm = blockIdx.y * 128;
    int tid = threadIdx.x;
    int tx = tid & 15, ty = tid >> 4;

    if (tid < 128) { sInitH[tid] = hInit[tid]; sInitC[tid] = cInit[tid]; }
    {
        int r = tid >> 1, c = tid & 1;
        sIdx[r][c] = indices[(size_t)lvl * NN * 2 + (size_t)(bm + r) * 2 + c];
    }
    __syncthreads();

    bool hasPrev = (lvl != 0);
    const float* prevH = outH + (size_t)(lvl - 1) * NN * DOUT;
    const float* prevC = outC + (size_t)(lvl - 1) * NN * DOUT;

    // A loader: rows m0, m1 fixed per thread for all tiles.
    int m0 = tid >> 2, c0 = tid & 3;
    int m1 = m0 + 64;
    int ci0[2], ci1[2];
    ci0[0] = sIdx[m0][0]; ci0[1] = sIdx[m0][1];
    ci1[0] = sIdx[m1][0]; ci1[1] = sIdx[m1][1];

    // B loader: col0 in [0,64), col1 in [64,80) for tid<64.
    int colBase = grp * 80;
    int bcol0 = tid >> 2, bc4 = (tid & 3) * 4;
    int bcol1 = 64 + (tid >> 2);
    bool hasB1 = (tid < 64);
    const float* Uc0 = g_Uperm + (size_t)(colBase + bcol0) * DIN + bc4;
    const float* Uc1 = g_Uperm + (size_t)(colBase + bcol1) * DIN + bc4;

    float acc[8][5];
#pragma unroll
    for (int i = 0; i < 8; i++)
#pragma unroll
        for (int w = 0; w < 5; w++) acc[i][w] = 0.f;

    float4 aS0, aS1, bS0, bS1;

    // ---- prologue tile 0 (half=0, kdbase=0) ----
    {
        int off = c0 * 4;
        aS0 = (hasPrev && ci0[0] >= 0) ? *(const float4*)&prevH[(size_t)ci0[0] * DOUT + off]
                                       : *(const float4*)&sInitH[off];
        aS1 = (hasPrev && ci1[0] >= 0) ? *(const float4*)&prevH[(size_t)ci1[0] * DOUT + off]
                                       : *(const float4*)&sInitH[off];
        bS0 = *(const float4*)Uc0;
        if (hasB1) bS1 = *(const float4*)Uc1;
#pragma unroll
        for (int j = 0; j < 4; j++) {
            As[0][c0 * 4 + j][m0] = f4c(aS0, j);
            As[0][c0 * 4 + j][m1] = f4c(aS1, j);
        }
        *(float4*)&Bs[0][bcol0][bc4] = bS0;
        if (hasB1) *(float4*)&Bs[0][bcol1][bc4] = bS1;
    }
    __syncthreads();

    int buf = 0;
    for (int t = 0; t < 16; t++) {
        if (t < 15) {
            int kt = (t + 1) * 16;
            int half = (kt >= 128) ? 1 : 0;
            int off = (kt & 127) + c0 * 4;
            int a0i = ci0[half], a1i = ci1[half];
            aS0 = (hasPrev && a0i >= 0) ? *(const float4*)&prevH[(size_t)a0i * DOUT + off]
                                        : *(const float4*)&sInitH[off];
            aS1 = (hasPrev && a1i >= 0) ? *(const float4*)&prevH[(size_t)a1i * DOUT + off]
                                        : *(const float4*)&sInitH[off];
            bS0 = *(const float4*)(Uc0 + kt);
            if (hasB1) bS1 = *(const float4*)(Uc1 + kt);
        }
#pragma unroll
        for (int kk4 = 0; kk4 < 4; kk4++) {
            float4 b4[5];
#pragma unroll
            for (int w = 0; w < 5; w++)
                b4[w] = *(const float4*)&Bs[buf][tx * 5 + w][kk4 * 4];
#pragma unroll
            for (int j = 0; j < 4; j++) {
                int kk = kk4 * 4 + j;
                float4 a0 = *(const float4*)&As[buf][kk][ty * 4];
                float4 a1 = *(const float4*)&As[buf][kk][ty * 4 + 64];
                float a[8] = {a0.x, a0.y, a0.z, a0.w, a1.x, a1.y, a1.z, a1.w};
#pragma unroll
                for (int w = 0; w < 5; w++) {
                    float bv = f4c(b4[w], j);
#pragma unroll
                    for (int i = 0; i < 8; i++)
                        acc[i][w] = fmaf(a[i], bv, acc[i][w]);
                }
            }
        }
        if (t < 15) {
            int nb = buf ^ 1;
#pragma unroll
            for (int j = 0; j < 4; j++) {
                As[nb][c0 * 4 + j][m0] = f4c(aS0, j);
                As[nb][c0 * 4 + j][m1] = f4c(aS1, j);
            }
            *(float4*)&Bs[nb][bcol0][bc4] = bS0;
            if (hasB1) *(float4*)&Bs[nb][bcol1][bc4] = bS1;
        }
        __syncthreads();
        buf ^= 1;
    }

    // ---- fused LSTM gate epilogue ----
    int d = grp * 16 + tx;
#pragma unroll
    for (int i = 0; i < 8; i++) {
        int m = (i < 4) ? (ty * 4 + i) : (64 + ty * 4 + i - 4);
        int n = bm + m;
        const float4 wv = *(const float4*)&g_Wx[(((size_t)lvl * NN + n) << 9) + (d << 2)];
        // wv: x=f_x, y=i_x, z=u_x, w=o_x
        float f1 = sigmoidf_(wv.x + acc[i][0]);
        float f2 = sigmoidf_(wv.x + acc[i][1]);
        float ig = sigmoidf_(wv.y + acc[i][2]);
        float ug = tanhf(wv.z + acc[i][3]);
        float og = sigmoidf_(wv.w + acc[i][4]);

        int c0i = sIdx[m][0], c1i = sIdx[m][1];
        float cc0 = (hasPrev && c0i >= 0) ? prevC[(size_t)c0i * DOUT + d] : sInitC[d];
        float cc1 = (hasPrev && c1i >= 0) ? prevC[(size_t)c1i * DOUT + d] : sInitC[d];

        float nc = ig * ug + f1 * cc0 + f2 * cc1;
        float nh = og * tanhf(nc);

        size_t o = ((size_t)lvl * NN + n) * DOUT + d;
        outH[o] = nh;
        outC[o] = nc;
    }
}

extern "C" void kernel_launch(void* const* d_in, const int* in_sizes, int n_in,
                              void* d_out, int out_size) {
    const float* tensor = (const float*)d_in[0];   // [L, N, DIN]
    const int*   indices = (const int*)d_in[1];    // [L, N, 2]
    const float* h_init = (const float*)d_in[2];   // [1, DOUT]
    const float* c_init = (const float*)d_in[3];   // [1, DOUT]
    const float* W_w   = (const float*)d_in[4];    // [4*DOUT, DIN]
    const float* W_b   = (const float*)d_in[5];    // [4*DOUT]
    const float* U_f1  = (const float*)d_in[6];    // [DOUT, 2*DOUT]
    const float* U_f2  = (const float*)d_in[7];
    const float* U_iuo = (const float*)d_in[8];    // [3*DOUT, 2*DOUT]

    float* outH = (float*)d_out;                         // res_h [L,N,DOUT]
    float* outC = outH + (size_t)LL * NN * DOUT;         // res_c [L,N,DOUT]

    build_uperm<<<(NU * DIN + 255) / 256, 256>>>(U_f1, U_f2, U_iuo);

    dim3 pg(NWX / 128, LL * NN / 128);                   // (4, 1536)
    pre_gemm<<<pg, 256>>>(tensor, W_w, W_b);

    dim3 lg(DOUT / 16, NN / 128);                        // (8, 64)
    for (int lvl = 0; lvl < LL; lvl++) {
        level_kernel<<<lg, 256>>>(lvl, indices, h_init, c_init, outH, outC);
    }
}

// round 5
// speedup vs baseline: 1.4490x; 1.0019x over previous
#include <cuda_runtime.h>
#include <math.h>

#define LL 24
#define NN 8192
#define DIN 256
#define DOUT 128
#define NWX 512     // 4*DOUT
#define NU  640     // 5*DOUT

// Scratch: W_x for all levels, permuted layout [lvl][n][d][gate], gate=(f,i,u,o). 402 MB.
__device__ float g_Wx[(size_t)LL * NN * NWX];
// Permuted recurrent weights, column-major: [col][k], col = d*5 + w; w:0=f1,1=f2,2=i,3=u,4=o.
__device__ float g_Uperm[(size_t)NU * DIN];

__device__ __forceinline__ float sigmoidf_(float x) {
    return 1.0f / (1.0f + __expf(-x));
}

__device__ __forceinline__ float f4c(const float4 v, int j) {
    return j == 0 ? v.x : j == 1 ? v.y : j == 2 ? v.z : v.w;
}

__global__ void build_uperm(const float* __restrict__ Uf1,
                            const float* __restrict__ Uf2,
                            const float* __restrict__ Uiuo) {
    int t = blockIdx.x * blockDim.x + threadIdx.x;
    if (t >= NU * DIN) return;
    int j = t / DIN;       // col
    int k = t - j * DIN;
    int d = j / 5;
    int w = j - d * 5;
    float v;
    if (w == 0)      v = Uf1[d * DIN + k];
    else if (w == 1) v = Uf2[d * DIN + k];
    else             v = Uiuo[((w - 2) * DOUT + d) * DIN + k];
    g_Uperm[t] = v;
}

// ---------------------------------------------------------------------------
// pre_gemm: W_x = X @ Ww.T + Wb, permuted output cols c = d*4+g.
// M=196608, N=512, K=256. BM=128, BN=128, BK=16. 256 thr, 8x8/thread.
// Smem [BK][BM] both sides, float4 fragment reads, double buffered.
// ---------------------------------------------------------------------------
__global__ __launch_bounds__(256, 2) void pre_gemm(const float* __restrict__ X,
                                                   const float* __restrict__ Ww,
                                                   const float* __restrict__ Wb) {
    __shared__ float As[2][16][132];
    __shared__ float Bs[2][16][132];

    int bm = blockIdx.y * 128;
    int bn = blockIdx.x * 128;
    int tid = threadIdx.x;
    int tx = tid & 15, ty = tid >> 4;

    // loader: tasks u = tid, tid+256 ; m = u>>2 (0..127), c = u&3 (16B chunk of 16-k tile)
    int m0 = tid >> 2, c0 = tid & 3;
    int m1 = m0 + 64;
    // permuted col -> original Ww row
    int cg0 = bn + m0, cg1 = bn + m1;
    int brow0 = ((cg0 & 3) << 7) + (cg0 >> 2);
    int brow1 = ((cg1 & 3) << 7) + (cg1 >> 2);

    const float* Xa0 = X + (size_t)(bm + m0) * DIN + c0 * 4;
    const float* Xa1 = X + (size_t)(bm + m1) * DIN + c0 * 4;
    const float* Wb0 = Ww + (size_t)brow0 * DIN + c0 * 4;
    const float* Wb1 = Ww + (size_t)brow1 * DIN + c0 * 4;

    float acc[8][8];
#pragma unroll
    for (int i = 0; i < 8; i++)
#pragma unroll
        for (int j = 0; j < 8; j++) acc[i][j] = 0.f;

    float4 aS0, aS1, bS0, bS1;
    aS0 = *(const float4*)Xa0;  aS1 = *(const float4*)Xa1;
    bS0 = *(const float4*)Wb0;  bS1 = *(const float4*)Wb1;
#pragma unroll
    for (int j = 0; j < 4; j++) {
        As[0][c0 * 4 + j][m0] = f4c(aS0, j);
        As[0][c0 * 4 + j][m1] = f4c(aS1, j);
        Bs[0][c0 * 4 + j][m0] = f4c(bS0, j);
        Bs[0][c0 * 4 + j][m1] = f4c(bS1, j);
    }
    __syncthreads();

    int buf = 0;
    for (int t = 0; t < 16; t++) {
        if (t < 15) {
            int kt = (t + 1) * 16;
            aS0 = *(const float4*)(Xa0 + kt);
            aS1 = *(const float4*)(Xa1 + kt);
            bS0 = *(const float4*)(Wb0 + kt);
            bS1 = *(const float4*)(Wb1 + kt);
        }
#pragma unroll
        for (int kk = 0; kk < 16; kk++) {
            float4 a0 = *(const float4*)&As[buf][kk][ty * 4];
            float4 a1 = *(const float4*)&As[buf][kk][ty * 4 + 64];
            float4 b0 = *(const float4*)&Bs[buf][kk][tx * 4];
            float4 b1 = *(const float4*)&Bs[buf][kk][tx * 4 + 64];
            float a[8] = {a0.x, a0.y, a0.z, a0.w, a1.x, a1.y, a1.z, a1.w};
            float b[8] = {b0.x, b0.y, b0.z, b0.w, b1.x, b1.y, b1.z, b1.w};
#pragma unroll
            for (int i = 0; i < 8; i++)
#pragma unroll
                for (int j = 0; j < 8; j++) acc[i][j] = fmaf(a[i], b[j], acc[i][j]);
        }
        if (t < 15) {
            int nb = buf ^ 1;
#pragma unroll
            for (int j = 0; j < 4; j++) {
                As[nb][c0 * 4 + j][m0] = f4c(aS0, j);
                As[nb][c0 * 4 + j][m1] = f4c(aS1, j);
                Bs[nb][c0 * 4 + j][m0] = f4c(bS0, j);
                Bs[nb][c0 * 4 + j][m1] = f4c(bS1, j);
            }
        }
        __syncthreads();
        buf ^= 1;
    }

    // epilogue: bias + store, two float4 groups per row
    float wb0[4], wb1[4];
#pragma unroll
    for (int j = 0; j < 4; j++) {
        int ca = bn + tx * 4 + j;
        int cb = bn + 64 + tx * 4 + j;
        wb0[j] = Wb[((ca & 3) << 7) + (ca >> 2)];
        wb1[j] = Wb[((cb & 3) << 7) + (cb >> 2)];
    }
#pragma unroll
    for (int i = 0; i < 8; i++) {
        int m = (i < 4) ? (ty * 4 + i) : (64 + ty * 4 + i - 4);
        size_t row = (size_t)(bm + m) * NWX;
        float4 o0, o1;
        o0.x = acc[i][0] + wb0[0]; o0.y = acc[i][1] + wb0[1];
        o0.z = acc[i][2] + wb0[2]; o0.w = acc[i][3] + wb0[3];
        o1.x = acc[i][4] + wb1[0]; o1.y = acc[i][5] + wb1[1];
        o1.z = acc[i][6] + wb1[2]; o1.w = acc[i][7] + wb1[3];
        *(float4*)&g_Wx[row + bn + tx * 4] = o0;
        *(float4*)&g_Wx[row + bn + 64 + tx * 4] = o1;
    }
}

// ---------------------------------------------------------------------------
// level_kernel: gather child h -> [8192 x 640] GEMM -> fused LSTM gates.
// BM=128, BN=80, BK=16, 256 threads, 8x5/thread.
// As[BK][BM] (transpose-on-store from LDG.128 gather), Bs[BN][BK] (float4 k).
// ---------------------------------------------------------------------------
__global__ __launch_bounds__(256, 2) void level_kernel(
    int lvl,
    const int* __restrict__ indices,
    const float* __restrict__ hInit,
    const float* __restrict__ cInit,
    float* __restrict__ outH,
    float* __restrict__ outC)
{
    __shared__ float As[2][16][132];
    __shared__ float Bs[2][80][20];
    __shared__ int sIdx[128][2];
    __shared__ __align__(16) float sInitH[128];
    __shared__ __align__(16) float sInitC[128];

    int grp = blockIdx.x;                 // d-group block: dBase = grp*16
    int bm = blockIdx.y * 128;
    int tid = threadIdx.x;
    int tx = tid & 15, ty = tid >> 4;

    if (tid < 128) { sInitH[tid] = hInit[tid]; sInitC[tid] = cInit[tid]; }
    {
        int r = tid >> 1, c = tid & 1;
        sIdx[r][c] = indices[(size_t)lvl * NN * 2 + (size_t)(bm + r) * 2 + c];
    }
    __syncthreads();

    bool hasPrev = (lvl != 0);
    const float* prevH = outH + (size_t)(lvl - 1) * NN * DOUT;
    const float* prevC = outC + (size_t)(lvl - 1) * NN * DOUT;

    // A loader: rows m0, m1 fixed per thread for all tiles.
    int m0 = tid >> 2, c0 = tid & 3;
    int m1 = m0 + 64;
    int ci0[2], ci1[2];
    ci0[0] = sIdx[m0][0]; ci0[1] = sIdx[m0][1];
    ci1[0] = sIdx[m1][0]; ci1[1] = sIdx[m1][1];

    // B loader: col0 in [0,64), col1 in [64,80) for tid<64.
    int colBase = grp * 80;
    int bcol0 = tid >> 2, bc4 = (tid & 3) * 4;
    int bcol1 = 64 + (tid >> 2);
    bool hasB1 = (tid < 64);
    const float* Uc0 = g_Uperm + (size_t)(colBase + bcol0) * DIN + bc4;
    const float* Uc1 = g_Uperm + (size_t)(colBase + bcol1) * DIN + bc4;

    float acc[8][5];
#pragma unroll
    for (int i = 0; i < 8; i++)
#pragma unroll
        for (int w = 0; w < 5; w++) acc[i][w] = 0.f;

    float4 aS0, aS1, bS0, bS1;

    // ---- prologue tile 0 (half=0, kdbase=0) ----
    {
        int off = c0 * 4;
        aS0 = (hasPrev && ci0[0] >= 0) ? *(const float4*)&prevH[(size_t)ci0[0] * DOUT + off]
                                       : *(const float4*)&sInitH[off];
        aS1 = (hasPrev && ci1[0] >= 0) ? *(const float4*)&prevH[(size_t)ci1[0] * DOUT + off]
                                       : *(const float4*)&sInitH[off];
        bS0 = *(const float4*)Uc0;
        if (hasB1) bS1 = *(const float4*)Uc1;
#pragma unroll
        for (int j = 0; j < 4; j++) {
            As[0][c0 * 4 + j][m0] = f4c(aS0, j);
            As[0][c0 * 4 + j][m1] = f4c(aS1, j);
        }
        *(float4*)&Bs[0][bcol0][bc4] = bS0;
        if (hasB1) *(float4*)&Bs[0][bcol1][bc4] = bS1;
    }
    __syncthreads();

    int buf = 0;
    for (int t = 0; t < 16; t++) {
        if (t < 15) {
            int kt = (t + 1) * 16;
            int half = (kt >= 128) ? 1 : 0;
            int off = (kt & 127) + c0 * 4;
            int a0i = ci0[half], a1i = ci1[half];
            aS0 = (hasPrev && a0i >= 0) ? *(const float4*)&prevH[(size_t)a0i * DOUT + off]
                                        : *(const float4*)&sInitH[off];
            aS1 = (hasPrev && a1i >= 0) ? *(const float4*)&prevH[(size_t)a1i * DOUT + off]
                                        : *(const float4*)&sInitH[off];
            bS0 = *(const float4*)(Uc0 + kt);
            if (hasB1) bS1 = *(const float4*)(Uc1 + kt);
        }
#pragma unroll
        for (int kk4 = 0; kk4 < 4; kk4++) {
            float4 b4[5];
#pragma unroll
            for (int w = 0; w < 5; w++)
                b4[w] = *(const float4*)&Bs[buf][tx * 5 + w][kk4 * 4];
#pragma unroll
            for (int j = 0; j < 4; j++) {
                int kk = kk4 * 4 + j;
                float4 a0 = *(const float4*)&As[buf][kk][ty * 4];
                float4 a1 = *(const float4*)&As[buf][kk][ty * 4 + 64];
                float a[8] = {a0.x, a0.y, a0.z, a0.w, a1.x, a1.y, a1.z, a1.w};
#pragma unroll
                for (int w = 0; w < 5; w++) {
                    float bv = f4c(b4[w], j);
#pragma unroll
                    for (int i = 0; i < 8; i++)
                        acc[i][w] = fmaf(a[i], bv, acc[i][w]);
                }
            }
        }
        if (t < 15) {
            int nb = buf ^ 1;
#pragma unroll
            for (int j = 0; j < 4; j++) {
                As[nb][c0 * 4 + j][m0] = f4c(aS0, j);
                As[nb][c0 * 4 + j][m1] = f4c(aS1, j);
            }
            *(float4*)&Bs[nb][bcol0][bc4] = bS0;
            if (hasB1) *(float4*)&Bs[nb][bcol1][bc4] = bS1;
        }
        __syncthreads();
        buf ^= 1;
    }

    // ---- fused LSTM gate epilogue ----
    int d = grp * 16 + tx;
#pragma unroll
    for (int i = 0; i < 8; i++) {
        int m = (i < 4) ? (ty * 4 + i) : (64 + ty * 4 + i - 4);
        int n = bm + m;
        const float4 wv = *(const float4*)&g_Wx[(((size_t)lvl * NN + n) << 9) + (d << 2)];
        // wv: x=f_x, y=i_x, z=u_x, w=o_x
        float f1 = sigmoidf_(wv.x + acc[i][0]);
        float f2 = sigmoidf_(wv.x + acc[i][1]);
        float ig = sigmoidf_(wv.y + acc[i][2]);
        float ug = tanhf(wv.z + acc[i][3]);
        float og = sigmoidf_(wv.w + acc[i][4]);

        int c0i = sIdx[m][0], c1i = sIdx[m][1];
        float cc0 = (hasPrev && c0i >= 0) ? prevC[(size_t)c0i * DOUT + d] : sInitC[d];
        float cc1 = (hasPrev && c1i >= 0) ? prevC[(size_t)c1i * DOUT + d] : sInitC[d];

        float nc = ig * ug + f1 * cc0 + f2 * cc1;
        float nh = og * tanhf(nc);

        size_t o = ((size_t)lvl * NN + n) * DOUT + d;
        outH[o] = nh;
        outC[o] = nc;
    }
}

extern "C" void kernel_launch(void* const* d_in, const int* in_sizes, int n_in,
                              void* d_out, int out_size) {
    const float* tensor = (const float*)d_in[0];   // [L, N, DIN]
    const int*   indices = (const int*)d_in[1];    // [L, N, 2]
    const float* h_init = (const float*)d_in[2];   // [1, DOUT]
    const float* c_init = (const float*)d_in[3];   // [1, DOUT]
    const float* W_w   = (const float*)d_in[4];    // [4*DOUT, DIN]
    const float* W_b   = (const float*)d_in[5];    // [4*DOUT]
    const float* U_f1  = (const float*)d_in[6];    // [DOUT, 2*DOUT]
    const float* U_f2  = (const float*)d_in[7];
    const float* U_iuo = (const float*)d_in[8];    // [3*DOUT, 2*DOUT]

    float* outH = (float*)d_out;                         // res_h [L,N,DOUT]
    float* outC = outH + (size_t)LL * NN * DOUT;         // res_c [L,N,DOUT]

    build_uperm<<<(NU * DIN + 255) / 256, 256>>>(U_f1, U_f2, U_iuo);

    dim3 pg(NWX / 128, LL * NN / 128);                   // (4, 1536)
    pre_gemm<<<pg, 256>>>(tensor, W_w, W_b);

    dim3 lg(DOUT / 16, NN / 128);                        // (8, 64)
    for (int lvl = 0; lvl < LL; lvl++) {
        level_kernel<<<lg, 256>>>(lvl, indices, h_init, c_init, outH, outC);
    }
}

// round 6
// speedup vs baseline: 1.7874x; 1.2335x over previous
#include <cuda_runtime.h>
#include <math.h>

#define LL 24
#define NN 8192
#define DIN 256
#define DOUT 128
#define NWX 512     // 4*DOUT
#define NP  1280    // 2 halves * 5 gates * 128

// W_x for all levels, permuted layout [lvl][n][d][gate], gate=(f,i,u,o). 402 MB.
__device__ float g_Wx[(size_t)LL * NN * NWX];
// Upair: rows c = half*640 + w*128 + d, cols k (0..127). Row-major [c][k].
__device__ float g_Upair[(size_t)NP * 128];
// P scratch: [node][c], c as above. 42 MB.
__device__ float g_P[(size_t)NN * NP];
// Pinit[c] = dot(h_init, Upair[c])
__device__ float g_Pinit[NP];

__device__ __forceinline__ float sigmoidf_(float x) {
    return 1.0f / (1.0f + __expf(-x));
}

__device__ __forceinline__ float f4c(const float4 v, int j) {
    return j == 0 ? v.x : j == 1 ? v.y : j == 2 ? v.z : v.w;
}

// Upair row c: half=c/640, r=c%640, w=r/128, d=r%128, source col = half*128+k.
__global__ void build_upair(const float* __restrict__ Uf1,
                            const float* __restrict__ Uf2,
                            const float* __restrict__ Uiuo) {
    int t = blockIdx.x * blockDim.x + threadIdx.x;
    if (t >= NP * 128) return;
    int c = t >> 7;
    int k = t & 127;
    int half = c / 640;
    int r = c - half * 640;
    int w = r >> 7;
    int d = r & 127;
    int sc = half * 128 + k;
    float v;
    if (w == 0)      v = Uf1[d * DIN + sc];
    else if (w == 1) v = Uf2[d * DIN + sc];
    else             v = Uiuo[((w - 2) * DOUT + d) * DIN + sc];
    g_Upair[t] = v;
}

__global__ void build_pinit(const float* __restrict__ hInit) {
    int c = blockIdx.x * blockDim.x + threadIdx.x;
    if (c >= NP) return;
    float s = 0.f;
    const float* row = g_Upair + (size_t)c * 128;
#pragma unroll 8
    for (int k = 0; k < 128; k++) s = fmaf(hInit[k], row[k], s);
    g_Pinit[c] = s;
}

// ---------------------------------------------------------------------------
// pre_gemm: W_x = X @ Ww.T + Wb, permuted output cols c = d*4+g.
// M=196608, N=512, K=256. BM=128, BN=128, BK=16. 256 thr, 8x8/thread.
// ---------------------------------------------------------------------------
__global__ __launch_bounds__(256, 2) void pre_gemm(const float* __restrict__ X,
                                                   const float* __restrict__ Ww,
                                                   const float* __restrict__ Wb) {
    __shared__ float As[2][16][132];
    __shared__ float Bs[2][16][132];

    int bm = blockIdx.y * 128;
    int bn = blockIdx.x * 128;
    int tid = threadIdx.x;
    int tx = tid & 15, ty = tid >> 4;

    int m0 = tid >> 2, c0 = tid & 3;
    int m1 = m0 + 64;
    int cg0 = bn + m0, cg1 = bn + m1;
    int brow0 = ((cg0 & 3) << 7) + (cg0 >> 2);
    int brow1 = ((cg1 & 3) << 7) + (cg1 >> 2);

    const float* Xa0 = X + (size_t)(bm + m0) * DIN + c0 * 4;
    const float* Xa1 = X + (size_t)(bm + m1) * DIN + c0 * 4;
    const float* Wb0 = Ww + (size_t)brow0 * DIN + c0 * 4;
    const float* Wb1 = Ww + (size_t)brow1 * DIN + c0 * 4;

    float acc[8][8];
#pragma unroll
    for (int i = 0; i < 8; i++)
#pragma unroll
        for (int j = 0; j < 8; j++) acc[i][j] = 0.f;

    float4 aS0, aS1, bS0, bS1;
    aS0 = *(const float4*)Xa0;  aS1 = *(const float4*)Xa1;
    bS0 = *(const float4*)Wb0;  bS1 = *(const float4*)Wb1;
#pragma unroll
    for (int j = 0; j < 4; j++) {
        As[0][c0 * 4 + j][m0] = f4c(aS0, j);
        As[0][c0 * 4 + j][m1] = f4c(aS1, j);
        Bs[0][c0 * 4 + j][m0] = f4c(bS0, j);
        Bs[0][c0 * 4 + j][m1] = f4c(bS1, j);
    }
    __syncthreads();

    int buf = 0;
    for (int t = 0; t < 16; t++) {
        if (t < 15) {
            int kt = (t + 1) * 16;
            aS0 = *(const float4*)(Xa0 + kt);
            aS1 = *(const float4*)(Xa1 + kt);
            bS0 = *(const float4*)(Wb0 + kt);
            bS1 = *(const float4*)(Wb1 + kt);
        }
#pragma unroll
        for (int kk = 0; kk < 16; kk++) {
            float4 a0 = *(const float4*)&As[buf][kk][ty * 4];
            float4 a1 = *(const float4*)&As[buf][kk][ty * 4 + 64];
            float4 b0 = *(const float4*)&Bs[buf][kk][tx * 4];
            float4 b1 = *(const float4*)&Bs[buf][kk][tx * 4 + 64];
            float a[8] = {a0.x, a0.y, a0.z, a0.w, a1.x, a1.y, a1.z, a1.w};
            float b[8] = {b0.x, b0.y, b0.z, b0.w, b1.x, b1.y, b1.z, b1.w};
#pragma unroll
            for (int i = 0; i < 8; i++)
#pragma unroll
                for (int j = 0; j < 8; j++) acc[i][j] = fmaf(a[i], b[j], acc[i][j]);
        }
        if (t < 15) {
            int nb = buf ^ 1;
#pragma unroll
            for (int j = 0; j < 4; j++) {
                As[nb][c0 * 4 + j][m0] = f4c(aS0, j);
                As[nb][c0 * 4 + j][m1] = f4c(aS1, j);
                Bs[nb][c0 * 4 + j][m0] = f4c(bS0, j);
                Bs[nb][c0 * 4 + j][m1] = f4c(bS1, j);
            }
        }
        __syncthreads();
        buf ^= 1;
    }

    float wb0[4], wb1[4];
#pragma unroll
    for (int j = 0; j < 4; j++) {
        int ca = bn + tx * 4 + j;
        int cb = bn + 64 + tx * 4 + j;
        wb0[j] = Wb[((ca & 3) << 7) + (ca >> 2)];
        wb1[j] = Wb[((cb & 3) << 7) + (cb >> 2)];
    }
#pragma unroll
    for (int i = 0; i < 8; i++) {
        int m = (i < 4) ? (ty * 4 + i) : (64 + ty * 4 + i - 4);
        size_t row = (size_t)(bm + m) * NWX;
        float4 o0, o1;
        o0.x = acc[i][0] + wb0[0]; o0.y = acc[i][1] + wb0[1];
        o0.z = acc[i][2] + wb0[2]; o0.w = acc[i][3] + wb0[3];
        o1.x = acc[i][4] + wb1[0]; o1.y = acc[i][5] + wb1[1];
        o1.z = acc[i][6] + wb1[2]; o1.w = acc[i][7] + wb1[3];
        *(float4*)&g_Wx[row + bn + tx * 4] = o0;
        *(float4*)&g_Wx[row + bn + 64 + tx * 4] = o1;
    }
}

// ---------------------------------------------------------------------------
// p_gemm: P = prevH @ Upair.T. M=8192, N=1280, K=128.
// BM=128, BN=128, BK=16, 256 thr, 8x8/thread, double buffered. Dense A & B.
// ---------------------------------------------------------------------------
__global__ __launch_bounds__(256, 2) void p_gemm(int lvl,
                                                 const float* __restrict__ outH) {
    __shared__ float As[2][16][132];
    __shared__ float Bs[2][16][132];

    const float* H = outH + (size_t)(lvl - 1) * NN * DOUT;

    int bm = blockIdx.y * 128;
    int bn = blockIdx.x * 128;
    int tid = threadIdx.x;
    int tx = tid & 15, ty = tid >> 4;

    int m0 = tid >> 2, c0 = tid & 3;
    int m1 = m0 + 64;

    const float* Ha0 = H + (size_t)(bm + m0) * 128 + c0 * 4;
    const float* Ha1 = H + (size_t)(bm + m1) * 128 + c0 * 4;
    const float* Ub0 = g_Upair + (size_t)(bn + m0) * 128 + c0 * 4;
    const float* Ub1 = g_Upair + (size_t)(bn + m1) * 128 + c0 * 4;

    float acc[8][8];
#pragma unroll
    for (int i = 0; i < 8; i++)
#pragma unroll
        for (int j = 0; j < 8; j++) acc[i][j] = 0.f;

    float4 aS0, aS1, bS0, bS1;
    aS0 = *(const float4*)Ha0;  aS1 = *(const float4*)Ha1;
    bS0 = *(const float4*)Ub0;  bS1 = *(const float4*)Ub1;
#pragma unroll
    for (int j = 0; j < 4; j++) {
        As[0][c0 * 4 + j][m0] = f4c(aS0, j);
        As[0][c0 * 4 + j][m1] = f4c(aS1, j);
        Bs[0][c0 * 4 + j][m0] = f4c(bS0, j);
        Bs[0][c0 * 4 + j][m1] = f4c(bS1, j);
    }
    __syncthreads();

    int buf = 0;
    for (int t = 0; t < 8; t++) {
        if (t < 7) {
            int kt = (t + 1) * 16;
            aS0 = *(const float4*)(Ha0 + kt);
            aS1 = *(const float4*)(Ha1 + kt);
            bS0 = *(const float4*)(Ub0 + kt);
            bS1 = *(const float4*)(Ub1 + kt);
        }
#pragma unroll
        for (int kk = 0; kk < 16; kk++) {
            float4 a0 = *(const float4*)&As[buf][kk][ty * 4];
            float4 a1 = *(const float4*)&As[buf][kk][ty * 4 + 64];
            float4 b0 = *(const float4*)&Bs[buf][kk][tx * 4];
            float4 b1 = *(const float4*)&Bs[buf][kk][tx * 4 + 64];
            float a[8] = {a0.x, a0.y, a0.z, a0.w, a1.x, a1.y, a1.z, a1.w};
            float b[8] = {b0.x, b0.y, b0.z, b0.w, b1.x, b1.y, b1.z, b1.w};
#pragma unroll
            for (int i = 0; i < 8; i++)
#pragma unroll
                for (int j = 0; j < 8; j++) acc[i][j] = fmaf(a[i], b[j], acc[i][j]);
        }
        if (t < 7) {
            int nb = buf ^ 1;
#pragma unroll
            for (int j = 0; j < 4; j++) {
                As[nb][c0 * 4 + j][m0] = f4c(aS0, j);
                As[nb][c0 * 4 + j][m1] = f4c(aS1, j);
                Bs[nb][c0 * 4 + j][m0] = f4c(bS0, j);
                Bs[nb][c0 * 4 + j][m1] = f4c(bS1, j);
            }
        }
        __syncthreads();
        buf ^= 1;
    }

#pragma unroll
    for (int i = 0; i < 8; i++) {
        int m = (i < 4) ? (ty * 4 + i) : (64 + ty * 4 + i - 4);
        size_t row = (size_t)(bm + m) * NP;
        float4 o0, o1;
        o0.x = acc[i][0]; o0.y = acc[i][1]; o0.z = acc[i][2]; o0.w = acc[i][3];
        o1.x = acc[i][4]; o1.y = acc[i][5]; o1.z = acc[i][6]; o1.w = acc[i][7];
        *(float4*)&g_P[row + bn + tx * 4] = o0;
        *(float4*)&g_P[row + bn + 64 + tx * 4] = o1;
    }
}

// ---------------------------------------------------------------------------
// epilogue: gather 2 P-rows per node + W_x -> gates -> H/C. Memory-bound.
// Block 256 = 2 nodes x 128 dims. Grid NN/2 per level.
// ---------------------------------------------------------------------------
__global__ __launch_bounds__(256) void epilogue_kernel(
    int lvl,
    const int* __restrict__ indices,
    const float* __restrict__ cInit,
    float* __restrict__ outH,
    float* __restrict__ outC)
{
    int tid = threadIdx.x;
    int n = blockIdx.x * 2 + (tid >> 7);
    int d = tid & 127;

    int i0 = indices[((size_t)lvl * NN + n) * 2 + 0];
    int i1 = indices[((size_t)lvl * NN + n) * 2 + 1];
    bool L0 = (lvl == 0);

    float p0[5], p1[5];
    if (!L0 && i0 >= 0) {
        const float* r = g_P + (size_t)i0 * NP;
#pragma unroll
        for (int w = 0; w < 5; w++) p0[w] = r[w * 128 + d];
    } else {
#pragma unroll
        for (int w = 0; w < 5; w++) p0[w] = g_Pinit[w * 128 + d];
    }
    if (!L0 && i1 >= 0) {
        const float* r = g_P + (size_t)i1 * NP + 640;
#pragma unroll
        for (int w = 0; w < 5; w++) p1[w] = r[w * 128 + d];
    } else {
#pragma unroll
        for (int w = 0; w < 5; w++) p1[w] = g_Pinit[640 + w * 128 + d];
    }

    const float4 wv = *(const float4*)&g_Wx[(((size_t)lvl * NN + n) << 9) + (d << 2)];
    // wv: x=f_x, y=i_x, z=u_x, w=o_x
    float f1 = sigmoidf_(wv.x + p0[0] + p1[0]);
    float f2 = sigmoidf_(wv.x + p0[1] + p1[1]);
    float ig = sigmoidf_(wv.y + p0[2] + p1[2]);
    float ug = tanhf(wv.z + p0[3] + p1[3]);
    float og = sigmoidf_(wv.w + p0[4] + p1[4]);

    const float* prevC = outC + (size_t)(lvl - 1) * NN * DOUT;
    float cc0 = (!L0 && i0 >= 0) ? prevC[(size_t)i0 * DOUT + d] : cInit[d];
    float cc1 = (!L0 && i1 >= 0) ? prevC[(size_t)i1 * DOUT + d] : cInit[d];

    float nc = ig * ug + f1 * cc0 + f2 * cc1;
    float nh = og * tanhf(nc);

    size_t o = ((size_t)lvl * NN + n) * DOUT + d;
    outH[o] = nh;
    outC[o] = nc;
}

extern "C" void kernel_launch(void* const* d_in, const int* in_sizes, int n_in,
                              void* d_out, int out_size) {
    const float* tensor = (const float*)d_in[0];   // [L, N, DIN]
    const int*   indices = (const int*)d_in[1];    // [L, N, 2]
    const float* h_init = (const float*)d_in[2];   // [1, DOUT]
    const float* c_init = (const float*)d_in[3];   // [1, DOUT]
    const float* W_w   = (const float*)d_in[4];    // [4*DOUT, DIN]
    const float* W_b   = (const float*)d_in[5];    // [4*DOUT]
    const float* U_f1  = (const float*)d_in[6];    // [DOUT, 2*DOUT]
    const float* U_f2  = (const float*)d_in[7];
    const float* U_iuo = (const float*)d_in[8];    // [3*DOUT, 2*DOUT]

    float* outH = (float*)d_out;                         // res_h [L,N,DOUT]
    float* outC = outH + (size_t)LL * NN * DOUT;         // res_c [L,N,DOUT]

    build_upair<<<(NP * 128 + 255) / 256, 256>>>(U_f1, U_f2, U_iuo);
    build_pinit<<<(NP + 255) / 256, 256>>>(h_init);

    dim3 pg(NWX / 128, LL * NN / 128);                   // (4, 1536)
    pre_gemm<<<pg, 256>>>(tensor, W_w, W_b);

    dim3 gg(NP / 128, NN / 128);                         // (10, 64)
    for (int lvl = 0; lvl < LL; lvl++) {
        if (lvl > 0) p_gemm<<<gg, 256>>>(lvl, outH);
        epilogue_kernel<<<NN / 2, 256>>>(lvl, indices, c_init, outH, outC);
    }
}

// round 9
// speedup vs baseline: 2.8374x; 1.5875x over previous
#include <cuda_runtime.h>
#include <cuda_bf16.h>
#include <cstdint>
#include <math.h>

#define LL 24
#define NN 8192
#define DIN 256
#define DOUT 128
#define NWX 512     // 4*DOUT
#define NP  1280    // 2 halves * 5 gates * 128

// ---------------- device globals ----------------
__device__ float g_Wx[(size_t)LL * NN * NWX];            // [lvl*NN+n][c], c=d*4+gate
__device__ float g_P[(size_t)NN * NP];
__device__ float g_Pinit[NP];
__device__ float g_Upair[(size_t)NP * 128];              // fp32 (for Pinit)
__device__ float g_biasPerm[NWX];
__device__ __nv_bfloat16 g_Ahi[(size_t)LL * NN * DIN];   // tensor split
__device__ __nv_bfloat16 g_Alo[(size_t)LL * NN * DIN];
__device__ __nv_bfloat16 g_Bwhi[(size_t)NWX * DIN];      // permuted Ww split
__device__ __nv_bfloat16 g_Bwlo[(size_t)NWX * DIN];
__device__ __nv_bfloat16 g_Uphi[(size_t)NP * 128];
__device__ __nv_bfloat16 g_Uplo[(size_t)NP * 128];
__device__ __nv_bfloat16 g_Hhi[(size_t)NN * DOUT];       // prev-level h split
__device__ __nv_bfloat16 g_Hlo[(size_t)NN * DOUT];

__device__ __forceinline__ float sigmoidf_(float x) {
    return 1.0f / (1.0f + __expf(-x));
}

__device__ __forceinline__ uint32_t smem_to_u32(const void* p) {
    uint32_t a;
    asm("{ .reg .u64 t; cvta.to.shared.u64 t, %1; cvt.u32.u64 %0, t; }" : "=r"(a) : "l"(p));
    return a;
}

#define CP_COMMIT() asm volatile("cp.async.commit_group;" ::: "memory")
__device__ __forceinline__ void cpa16(uint32_t d, const void* s) {
    asm volatile("cp.async.cg.shared.global [%0], [%1], 16;" :: "r"(d), "l"(s));
}
__device__ __forceinline__ void ldm_x4(uint32_t a, uint32_t& r0, uint32_t& r1,
                                       uint32_t& r2, uint32_t& r3) {
    asm volatile("ldmatrix.sync.aligned.m8n8.x4.shared.b16 {%0,%1,%2,%3}, [%4];"
                 : "=r"(r0), "=r"(r1), "=r"(r2), "=r"(r3) : "r"(a));
}
__device__ __forceinline__ void mma16816(float* c, const uint32_t* a, const uint32_t* b) {
    asm volatile(
        "mma.sync.aligned.m16n8k16.row.col.f32.bf16.bf16.f32 "
        "{%0,%1,%2,%3}, {%4,%5,%6,%7}, {%8,%9}, {%0,%1,%2,%3};"
        : "+f"(c[0]), "+f"(c[1]), "+f"(c[2]), "+f"(c[3])
        : "r"(a[0]), "r"(a[1]), "r"(a[2]), "r"(a[3]), "r"(b[0]), "r"(b[1]));
}

// ---------------- weight / input prep (globals referenced in device code) ----
__global__ void build_asplit(const float* __restrict__ X) {
    size_t i = (size_t)blockIdx.x * 256 + threadIdx.x;   // one float4 per thread
    float4 v = ((const float4*)X)[i];
    __nv_bfloat16 hx = __float2bfloat16(v.x), hy = __float2bfloat16(v.y);
    __nv_bfloat16 hz = __float2bfloat16(v.z), hw = __float2bfloat16(v.w);
    union { __nv_bfloat16 b[4]; uint2 u; } hi, lo;
    hi.b[0] = hx; hi.b[1] = hy; hi.b[2] = hz; hi.b[3] = hw;
    lo.b[0] = __float2bfloat16(v.x - __bfloat162float(hx));
    lo.b[1] = __float2bfloat16(v.y - __bfloat162float(hy));
    lo.b[2] = __float2bfloat16(v.z - __bfloat162float(hz));
    lo.b[3] = __float2bfloat16(v.w - __bfloat162float(hw));
    *(uint2*)&g_Ahi[i * 4] = hi.u;
    *(uint2*)&g_Alo[i * 4] = lo.u;
}

__global__ void build_bw(const float* __restrict__ Ww, const float* __restrict__ Wb) {
    int t = blockIdx.x * blockDim.x + threadIdx.x;
    if (t < NWX) g_biasPerm[t] = Wb[((t & 3) << 7) + (t >> 2)];
    if (t >= NWX * DIN) return;
    int c = t >> 8, k = t & 255;
    int orig = ((c & 3) << 7) + (c >> 2);
    float v = Ww[orig * DIN + k];
    __nv_bfloat16 h = __float2bfloat16(v);
    g_Bwhi[t] = h;
    g_Bwlo[t] = __float2bfloat16(v - __bfloat162float(h));
}

__global__ void build_upair(const float* __restrict__ Uf1,
                            const float* __restrict__ Uf2,
                            const float* __restrict__ Uiuo) {
    int t = blockIdx.x * blockDim.x + threadIdx.x;
    if (t >= NP * 128) return;
    int c = t >> 7;
    int k = t & 127;
    int half = c / 640;
    int r = c - half * 640;
    int w = r >> 7;
    int d = r & 127;
    int sc = half * 128 + k;
    float v;
    if (w == 0)      v = Uf1[d * DIN + sc];
    else if (w == 1) v = Uf2[d * DIN + sc];
    else             v = Uiuo[((w - 2) * DOUT + d) * DIN + sc];
    g_Upair[t] = v;
    __nv_bfloat16 h = __float2bfloat16(v);
    g_Uphi[t] = h;
    g_Uplo[t] = __float2bfloat16(v - __bfloat162float(h));
}

__global__ void build_pinit(const float* __restrict__ hInit) {
    int c = blockIdx.x * blockDim.x + threadIdx.x;
    if (c >= NP) return;
    float s = 0.f;
    const float* row = g_Upair + (size_t)c * 128;
#pragma unroll 8
    for (int k = 0; k < 128; k++) s = fmaf(hInit[k], row[k], s);
    g_Pinit[c] = s;
}

// ---------------- bf16 hi/lo mma.sync GEMM ----------------
// C[bm+128][bn+128] = A @ B^T (+bias). A/B bf16 hi+lo K-major, bound to
// device globals inside the kernel (MODE 0: pre-GEMM, MODE 1: level GEMM).
// Tiles: BM=BN=128, BK=32. 8 warps: wm=wid&1 (64 rows), wn=wid>>1 (32 cols).
// Smem row pitch 80B (32 bf16 + 8 pad).
#define SM_PITCH 80
#define SM_ARR   10240              // 128 rows * 80B
#define SM_BUF   40960              // Ahi,Alo,Bhi,Blo
#define SM_TOT   81920

template<int MODE>
__global__ __launch_bounds__(256) void mma_gemm() {
    constexpr int K   = (MODE == 0) ? DIN : DOUT;
    constexpr int nCh = K / 32;
    constexpr int ldc = (MODE == 0) ? NWX : NP;

    const __nv_bfloat16* __restrict__ Ahi = (MODE == 0) ? g_Ahi : g_Hhi;
    const __nv_bfloat16* __restrict__ Alo = (MODE == 0) ? g_Alo : g_Hlo;
    const __nv_bfloat16* __restrict__ Bhi = (MODE == 0) ? g_Bwhi : g_Uphi;
    const __nv_bfloat16* __restrict__ Blo = (MODE == 0) ? g_Bwlo : g_Uplo;
    float* __restrict__ Cout = (MODE == 0) ? g_Wx : g_P;

    extern __shared__ char smem[];
    uint32_t sb = smem_to_u32(smem);
    int tid = threadIdx.x;
    int lane = tid & 31, wid = tid >> 5;
    int wm = wid & 1, wn = wid >> 1;
    int bn = blockIdx.x * 128;
    int bm = blockIdx.y * 128;

    float acc[4][4][4];
#pragma unroll
    for (int mi = 0; mi < 4; mi++)
#pragma unroll
        for (int ni = 0; ni < 4; ni++)
#pragma unroll
            for (int e = 0; e < 4; e++) acc[mi][ni][e] = 0.f;

    // cp.async: this thread handles chunks tid*2, tid*2+1 of each 128x32 tile.
    int ch0 = tid * 2;
    int rowA0 = ch0 >> 2, cc0 = (ch0 & 3);
    int rowA1 = (ch0 + 1) >> 2, cc1 = ((ch0 + 1) & 3);
    const __nv_bfloat16* gAhi0 = Ahi + (size_t)(bm + rowA0) * K + cc0 * 8;
    const __nv_bfloat16* gAhi1 = Ahi + (size_t)(bm + rowA1) * K + cc1 * 8;
    const __nv_bfloat16* gAlo0 = Alo + (size_t)(bm + rowA0) * K + cc0 * 8;
    const __nv_bfloat16* gAlo1 = Alo + (size_t)(bm + rowA1) * K + cc1 * 8;
    const __nv_bfloat16* gBhi0 = Bhi + (size_t)(bn + rowA0) * K + cc0 * 8;
    const __nv_bfloat16* gBhi1 = Bhi + (size_t)(bn + rowA1) * K + cc1 * 8;
    const __nv_bfloat16* gBlo0 = Blo + (size_t)(bn + rowA0) * K + cc0 * 8;
    const __nv_bfloat16* gBlo1 = Blo + (size_t)(bn + rowA1) * K + cc1 * 8;
    uint32_t s0 = (uint32_t)(rowA0 * SM_PITCH + cc0 * 16);
    uint32_t s1 = (uint32_t)(rowA1 * SM_PITCH + cc1 * 16);

#define LOAD_STAGE(t, b) do {                                              \
    uint32_t bo = sb + (uint32_t)(b) * SM_BUF;                             \
    int ko = (t) * 32;                                                     \
    cpa16(bo + s0,              gAhi0 + ko);                               \
    cpa16(bo + s1,              gAhi1 + ko);                               \
    cpa16(bo + SM_ARR + s0,     gAlo0 + ko);                               \
    cpa16(bo + SM_ARR + s1,     gAlo1 + ko);                               \
    cpa16(bo + 2*SM_ARR + s0,   gBhi0 + ko);                               \
    cpa16(bo + 2*SM_ARR + s1,   gBhi1 + ko);                               \
    cpa16(bo + 3*SM_ARR + s0,   gBlo0 + ko);                               \
    cpa16(bo + 3*SM_ARR + s1,   gBlo1 + ko);                               \
} while (0)

    // ldmatrix lane addressing
    int q = lane >> 3, r = lane & 7;
    uint32_t aLane = (uint32_t)(wm * 64 * SM_PITCH + (r + (q & 1) * 8) * SM_PITCH + (q >> 1) * 16);
    uint32_t bLane = (uint32_t)(wn * 32 * SM_PITCH + ((q >> 1) * 8 + r) * SM_PITCH + (q & 1) * 16);

    LOAD_STAGE(0, 0); CP_COMMIT();
    if (nCh > 1) { LOAD_STAGE(1, 1); CP_COMMIT(); }

    for (int t = 0; t < nCh; t++) {
        if (t == nCh - 1) asm volatile("cp.async.wait_group 0;" ::: "memory");
        else              asm volatile("cp.async.wait_group 1;" ::: "memory");
        __syncthreads();

        uint32_t base = sb + (uint32_t)(t & 1) * SM_BUF;
#pragma unroll
        for (int pass = 0; pass < 3; pass++) {
            uint32_t sA = base + ((pass == 2) ? (uint32_t)SM_ARR : 0u);
            uint32_t sB = base + 2u * SM_ARR + ((pass == 1) ? (uint32_t)SM_ARR : 0u);
#pragma unroll
            for (int ks = 0; ks < 2; ks++) {
                uint32_t a[4][4], b[4][2];
#pragma unroll
                for (int mi = 0; mi < 4; mi++)
                    ldm_x4(sA + aLane + mi * (16 * SM_PITCH) + ks * 32,
                           a[mi][0], a[mi][1], a[mi][2], a[mi][3]);
#pragma unroll
                for (int np = 0; np < 2; np++) {
                    uint32_t r0, r1, r2, r3;
                    ldm_x4(sB + bLane + np * (16 * SM_PITCH) + ks * 32, r0, r1, r2, r3);
                    b[2 * np][0] = r0; b[2 * np][1] = r1;
                    b[2 * np + 1][0] = r2; b[2 * np + 1][1] = r3;
                }
#pragma unroll
                for (int mi = 0; mi < 4; mi++)
#pragma unroll
                    for (int ni = 0; ni < 4; ni++)
                        mma16816(acc[mi][ni], a[mi], b[ni]);
            }
        }
        __syncthreads();
        if (t + 2 < nCh) { LOAD_STAGE(t + 2, t & 1); CP_COMMIT(); }
    }

    // epilogue
    int g = lane >> 2, tc = lane & 3;
#pragma unroll
    for (int mi = 0; mi < 4; mi++) {
        int row0 = bm + wm * 64 + mi * 16 + g;
#pragma unroll
        for (int ni = 0; ni < 4; ni++) {
            int col = bn + wn * 32 + ni * 8 + tc * 2;
            float b0 = 0.f, b1 = 0.f;
            if (MODE == 0) { b0 = g_biasPerm[col]; b1 = g_biasPerm[col + 1]; }
            float2 v0, v1;
            v0.x = acc[mi][ni][0] + b0; v0.y = acc[mi][ni][1] + b1;
            v1.x = acc[mi][ni][2] + b0; v1.y = acc[mi][ni][3] + b1;
            *(float2*)&Cout[(size_t)row0 * ldc + col] = v0;
            *(float2*)&Cout[(size_t)(row0 + 8) * ldc + col] = v1;
        }
    }
#undef LOAD_STAGE
}

// ---------------- LSTM gate epilogue ----------------
__global__ __launch_bounds__(256) void epilogue_kernel(
    int lvl,
    const int* __restrict__ indices,
    const float* __restrict__ cInit,
    float* __restrict__ outH,
    float* __restrict__ outC)
{
    int tid = threadIdx.x;
    int n = blockIdx.x * 2 + (tid >> 7);
    int d = tid & 127;

    int i0 = indices[((size_t)lvl * NN + n) * 2 + 0];
    int i1 = indices[((size_t)lvl * NN + n) * 2 + 1];
    bool L0 = (lvl == 0);

    float p0[5], p1[5];
    if (!L0 && i0 >= 0) {
        const float* rr = g_P + (size_t)i0 * NP;
#pragma unroll
        for (int w = 0; w < 5; w++) p0[w] = rr[w * 128 + d];
    } else {
#pragma unroll
        for (int w = 0; w < 5; w++) p0[w] = g_Pinit[w * 128 + d];
    }
    if (!L0 && i1 >= 0) {
        const float* rr = g_P + (size_t)i1 * NP + 640;
#pragma unroll
        for (int w = 0; w < 5; w++) p1[w] = rr[w * 128 + d];
    } else {
#pragma unroll
        for (int w = 0; w < 5; w++) p1[w] = g_Pinit[640 + w * 128 + d];
    }

    const float4 wv = *(const float4*)&g_Wx[(((size_t)lvl * NN + n) << 9) + (d << 2)];
    // wv: x=f_x, y=i_x, z=u_x, w=o_x
    float f1 = sigmoidf_(wv.x + p0[0] + p1[0]);
    float f2 = sigmoidf_(wv.x + p0[1] + p1[1]);
    float ig = sigmoidf_(wv.y + p0[2] + p1[2]);
    float ug = tanhf(wv.z + p0[3] + p1[3]);
    float og = sigmoidf_(wv.w + p0[4] + p1[4]);

    const float* prevC = outC + (size_t)(lvl - 1) * NN * DOUT;
    float cc0 = (!L0 && i0 >= 0) ? prevC[(size_t)i0 * DOUT + d] : cInit[d];
    float cc1 = (!L0 && i1 >= 0) ? prevC[(size_t)i1 * DOUT + d] : cInit[d];

    float nc = ig * ug + f1 * cc0 + f2 * cc1;
    float nh = og * tanhf(nc);

    size_t o = ((size_t)lvl * NN + n) * DOUT + d;
    outH[o] = nh;
    outC[o] = nc;

    // bf16 hi/lo split of h for the next level's tensor-core GEMM
    __nv_bfloat16 hh = __float2bfloat16(nh);
    g_Hhi[(size_t)n * DOUT + d] = hh;
    g_Hlo[(size_t)n * DOUT + d] = __float2bfloat16(nh - __bfloat162float(hh));
}

extern "C" void kernel_launch(void* const* d_in, const int* in_sizes, int n_in,
                              void* d_out, int out_size) {
    const float* tensor = (const float*)d_in[0];   // [L, N, DIN]
    const int*   indices = (const int*)d_in[1];    // [L, N, 2]
    const float* h_init = (const float*)d_in[2];   // [1, DOUT]
    const float* c_init = (const float*)d_in[3];   // [1, DOUT]
    const float* W_w   = (const float*)d_in[4];    // [4*DOUT, DIN]
    const float* W_b   = (const float*)d_in[5];    // [4*DOUT]
    const float* U_f1  = (const float*)d_in[6];    // [DOUT, 2*DOUT]
    const float* U_f2  = (const float*)d_in[7];
    const float* U_iuo = (const float*)d_in[8];    // [3*DOUT, 2*DOUT]

    float* outH = (float*)d_out;                         // res_h [L,N,DOUT]
    float* outC = outH + (size_t)LL * NN * DOUT;         // res_c [L,N,DOUT]

    cudaFuncSetAttribute(mma_gemm<0>, cudaFuncAttributeMaxDynamicSharedMemorySize, SM_TOT);
    cudaFuncSetAttribute(mma_gemm<1>, cudaFuncAttributeMaxDynamicSharedMemorySize, SM_TOT);

    build_asplit<<<(LL * NN * DIN / 4) / 256, 256>>>(tensor);
    build_bw<<<(NWX * DIN + 255) / 256, 256>>>(W_w, W_b);
    build_upair<<<(NP * 128 + 255) / 256, 256>>>(U_f1, U_f2, U_iuo);
    build_pinit<<<(NP + 255) / 256, 256>>>(h_init);

    // pre: W_x = X @ Ww^T + b.  M = L*N, N = 512, K = 256.
    {
        dim3 g(NWX / 128, (LL * NN) / 128);              // (4, 1536)
        mma_gemm<0><<<g, 256, SM_TOT>>>();
    }

    dim3 pg(NP / 128, NN / 128);                         // (10, 64)
    for (int lvl = 0; lvl < LL; lvl++) {
        if (lvl > 0) {
            mma_gemm<1><<<pg, 256, SM_TOT>>>();
        }
        epilogue_kernel<<<NN / 2, 256>>>(lvl, indices, c_init, outH, outC);
    }
}

// round 10
// speedup vs baseline: 3.8439x; 1.3548x over previous
#include <cuda_runtime.h>
#include <cuda_fp16.h>
#include <cstdint>
#include <math.h>

#define LL 24
#define NN 8192
#define DIN 256
#define DOUT 128
#define NWX 512     // 4*DOUT
#define NP  1280    // 2 halves * 5 gates * 128

// ---------------- device globals ----------------
__device__ float g_Wx[(size_t)LL * NN * NWX];            // [lvl*NN+n][c], c=d*4+gate
__device__ float g_P[(size_t)NN * NP];
__device__ float g_Pinit[NP];
__device__ float g_Upair[(size_t)NP * 128];              // fp32 (for Pinit)
__device__ float g_biasPerm[NWX];
__device__ __half g_Ah[(size_t)LL * NN * DIN];           // tensor, fp16
__device__ __half g_Bwhi[(size_t)NWX * DIN];             // permuted Ww, fp16 hi
__device__ __half g_Bwlo[(size_t)NWX * DIN];             // fp16 lo
__device__ __half g_Uphi[(size_t)NP * 128];
__device__ __half g_Uplo[(size_t)NP * 128];
__device__ __half g_Hh[(size_t)NN * DOUT];               // prev-level h, fp16

__device__ __forceinline__ float sigmoidf_(float x) {
    return 1.0f / (1.0f + __expf(-x));
}

__device__ __forceinline__ uint32_t smem_to_u32(const void* p) {
    uint32_t a;
    asm("{ .reg .u64 t; cvta.to.shared.u64 t, %1; cvt.u32.u64 %0, t; }" : "=r"(a) : "l"(p));
    return a;
}

#define CP_COMMIT() asm volatile("cp.async.commit_group;" ::: "memory")
__device__ __forceinline__ void cpa16(uint32_t d, const void* s) {
    asm volatile("cp.async.cg.shared.global [%0], [%1], 16;" :: "r"(d), "l"(s));
}
__device__ __forceinline__ void ldm_x4(uint32_t a, uint32_t& r0, uint32_t& r1,
                                       uint32_t& r2, uint32_t& r3) {
    asm volatile("ldmatrix.sync.aligned.m8n8.x4.shared.b16 {%0,%1,%2,%3}, [%4];"
                 : "=r"(r0), "=r"(r1), "=r"(r2), "=r"(r3) : "r"(a));
}
__device__ __forceinline__ void mma16816(float* c, const uint32_t* a, const uint32_t* b) {
    asm volatile(
        "mma.sync.aligned.m16n8k16.row.col.f32.f16.f16.f32 "
        "{%0,%1,%2,%3}, {%4,%5,%6,%7}, {%8,%9}, {%0,%1,%2,%3};"
        : "+f"(c[0]), "+f"(c[1]), "+f"(c[2]), "+f"(c[3])
        : "r"(a[0]), "r"(a[1]), "r"(a[2]), "r"(a[3]), "r"(b[0]), "r"(b[1]));
}

// ---------------- prep kernels (globals bound in device code) ----------------
__global__ void build_ah(const float* __restrict__ X) {
    size_t i = (size_t)blockIdx.x * 256 + threadIdx.x;   // one float4 per thread
    float4 v = ((const float4*)X)[i];
    union { __half h[4]; uint2 u; } o;
    o.h[0] = __float2half(v.x); o.h[1] = __float2half(v.y);
    o.h[2] = __float2half(v.z); o.h[3] = __float2half(v.w);
    *(uint2*)&g_Ah[i * 4] = o.u;
}

__global__ void build_bw(const float* __restrict__ Ww, const float* __restrict__ Wb) {
    int t = blockIdx.x * blockDim.x + threadIdx.x;
    if (t < NWX) g_biasPerm[t] = Wb[((t & 3) << 7) + (t >> 2)];
    if (t >= NWX * DIN) return;
    int c = t >> 8, k = t & 255;
    int orig = ((c & 3) << 7) + (c >> 2);
    float v = Ww[orig * DIN + k];
    __half h = __float2half(v);
    g_Bwhi[t] = h;
    g_Bwlo[t] = __float2half(v - __half2float(h));
}

__global__ void build_upair(const float* __restrict__ Uf1,
                            const float* __restrict__ Uf2,
                            const float* __restrict__ Uiuo) {
    int t = blockIdx.x * blockDim.x + threadIdx.x;
    if (t >= NP * 128) return;
    int c = t >> 7;
    int k = t & 127;
    int half = c / 640;
    int r = c - half * 640;
    int w = r >> 7;
    int d = r & 127;
    int sc = half * 128 + k;
    float v;
    if (w == 0)      v = Uf1[d * DIN + sc];
    else if (w == 1) v = Uf2[d * DIN + sc];
    else             v = Uiuo[((w - 2) * DOUT + d) * DIN + sc];
    g_Upair[t] = v;
    __half h = __float2half(v);
    g_Uphi[t] = h;
    g_Uplo[t] = __float2half(v - __half2float(h));
}

// one warp per output c, shuffle reduction
__global__ void build_pinit(const float* __restrict__ hInit) {
    int warp = (blockIdx.x * blockDim.x + threadIdx.x) >> 5;
    int lane = threadIdx.x & 31;
    if (warp >= NP) return;
    const float* row = g_Upair + (size_t)warp * 128;
    float s = 0.f;
#pragma unroll
    for (int k = 0; k < 4; k++) {
        int kk = lane + k * 32;
        s = fmaf(hInit[kk], row[kk], s);
    }
#pragma unroll
    for (int o = 16; o > 0; o >>= 1) s += __shfl_xor_sync(0xFFFFFFFF, s, o);
    if (lane == 0) g_Pinit[warp] = s;
}

// ---------------- fp16x2 mma.sync GEMM ----------------
// C[bm+128][bn+128] = A @ (Bhi+Blo)^T (+bias). A fp16, B fp16 hi+lo, K-major.
// MODE 0: X @ Ww -> g_Wx.  MODE 1: H @ Upair -> g_P.
// Tiles: BM=BN=128, BK=32. 8 warps: wm=wid&1 (64 rows), wn=wid>>1 (32 cols).
// Smem row pitch 80B (32 fp16 + pad). 3 arrays/stage: A, Bhi, Blo. 2 stages.
#define SM_PITCH 80
#define SM_ARR   10240              // 128 rows * 80B
#define SM_BUF   30720              // A, Bhi, Blo
#define SM_TOT   61440

template<int MODE>
__global__ __launch_bounds__(256, 2) void mma_gemm() {
    constexpr int K   = (MODE == 0) ? DIN : DOUT;
    constexpr int nCh = K / 32;
    constexpr int ldc = (MODE == 0) ? NWX : NP;

    const __half* __restrict__ A   = (MODE == 0) ? g_Ah : g_Hh;
    const __half* __restrict__ Bhi = (MODE == 0) ? g_Bwhi : g_Uphi;
    const __half* __restrict__ Blo = (MODE == 0) ? g_Bwlo : g_Uplo;
    float* __restrict__ Cout = (MODE == 0) ? g_Wx : g_P;

    extern __shared__ char smem[];
    uint32_t sb = smem_to_u32(smem);
    int tid = threadIdx.x;
    int lane = tid & 31, wid = tid >> 5;
    int wm = wid & 1, wn = wid >> 1;
    int bn = blockIdx.x * 128;
    int bm = blockIdx.y * 128;

    float acc[4][4][4];
#pragma unroll
    for (int mi = 0; mi < 4; mi++)
#pragma unroll
        for (int ni = 0; ni < 4; ni++)
#pragma unroll
            for (int e = 0; e < 4; e++) acc[mi][ni][e] = 0.f;

    // cp.async: 512 16B-chunks per 128x32 fp16 array; 2 chunks/thread/array.
    int ch0 = tid * 2;
    int rowA0 = ch0 >> 2, cc0 = (ch0 & 3);
    int rowA1 = (ch0 + 1) >> 2, cc1 = ((ch0 + 1) & 3);
    const __half* gA0 = A + (size_t)(bm + rowA0) * K + cc0 * 8;
    const __half* gA1 = A + (size_t)(bm + rowA1) * K + cc1 * 8;
    const __half* gBh0 = Bhi + (size_t)(bn + rowA0) * K + cc0 * 8;
    const __half* gBh1 = Bhi + (size_t)(bn + rowA1) * K + cc1 * 8;
    const __half* gBl0 = Blo + (size_t)(bn + rowA0) * K + cc0 * 8;
    const __half* gBl1 = Blo + (size_t)(bn + rowA1) * K + cc1 * 8;
    uint32_t s0 = (uint32_t)(rowA0 * SM_PITCH + cc0 * 16);
    uint32_t s1 = (uint32_t)(rowA1 * SM_PITCH + cc1 * 16);

#define LOAD_STAGE(t, b) do {                                              \
    uint32_t bo = sb + (uint32_t)(b) * SM_BUF;                             \
    int ko = (t) * 32;                                                     \
    cpa16(bo + s0,              gA0 + ko);                                 \
    cpa16(bo + s1,              gA1 + ko);                                 \
    cpa16(bo + SM_ARR + s0,     gBh0 + ko);                                \
    cpa16(bo + SM_ARR + s1,     gBh1 + ko);                                \
    cpa16(bo + 2*SM_ARR + s0,   gBl0 + ko);                                \
    cpa16(bo + 2*SM_ARR + s1,   gBl1 + ko);                                \
} while (0)

    // ldmatrix lane addressing (same as verified R8 kernel)
    int q = lane >> 3, r = lane & 7;
    uint32_t aLane = (uint32_t)(wm * 64 * SM_PITCH + (r + (q & 1) * 8) * SM_PITCH + (q >> 1) * 16);
    uint32_t bLane = (uint32_t)(wn * 32 * SM_PITCH + ((q >> 1) * 8 + r) * SM_PITCH + (q & 1) * 16);

    LOAD_STAGE(0, 0); CP_COMMIT();
    if (nCh > 1) { LOAD_STAGE(1, 1); CP_COMMIT(); }

    for (int t = 0; t < nCh; t++) {
        if (t == nCh - 1) asm volatile("cp.async.wait_group 0;" ::: "memory");
        else              asm volatile("cp.async.wait_group 1;" ::: "memory");
        __syncthreads();

        uint32_t base = sb + (uint32_t)(t & 1) * SM_BUF;
#pragma unroll
        for (int ks = 0; ks < 2; ks++) {
            uint32_t a[4][4], bh[4][2], bl[4][2];
#pragma unroll
            for (int mi = 0; mi < 4; mi++)
                ldm_x4(base + aLane + mi * (16 * SM_PITCH) + ks * 32,
                       a[mi][0], a[mi][1], a[mi][2], a[mi][3]);
#pragma unroll
            for (int np = 0; np < 2; np++) {
                uint32_t r0, r1, r2, r3;
                ldm_x4(base + SM_ARR + bLane + np * (16 * SM_PITCH) + ks * 32, r0, r1, r2, r3);
                bh[2 * np][0] = r0; bh[2 * np][1] = r1;
                bh[2 * np + 1][0] = r2; bh[2 * np + 1][1] = r3;
                ldm_x4(base + 2 * SM_ARR + bLane + np * (16 * SM_PITCH) + ks * 32, r0, r1, r2, r3);
                bl[2 * np][0] = r0; bl[2 * np][1] = r1;
                bl[2 * np + 1][0] = r2; bl[2 * np + 1][1] = r3;
            }
#pragma unroll
            for (int mi = 0; mi < 4; mi++)
#pragma unroll
                for (int ni = 0; ni < 4; ni++) {
                    mma16816(acc[mi][ni], a[mi], bh[ni]);
                    mma16816(acc[mi][ni], a[mi], bl[ni]);
                }
        }
        __syncthreads();
        if (t + 2 < nCh) { LOAD_STAGE(t + 2, t & 1); CP_COMMIT(); }
    }

    // epilogue
    int g = lane >> 2, tc = lane & 3;
#pragma unroll
    for (int mi = 0; mi < 4; mi++) {
        int row0 = bm + wm * 64 + mi * 16 + g;
#pragma unroll
        for (int ni = 0; ni < 4; ni++) {
            int col = bn + wn * 32 + ni * 8 + tc * 2;
            float b0 = 0.f, b1 = 0.f;
            if (MODE == 0) { b0 = g_biasPerm[col]; b1 = g_biasPerm[col + 1]; }
            float2 v0, v1;
            v0.x = acc[mi][ni][0] + b0; v0.y = acc[mi][ni][1] + b1;
            v1.x = acc[mi][ni][2] + b0; v1.y = acc[mi][ni][3] + b1;
            *(float2*)&Cout[(size_t)row0 * ldc + col] = v0;
            *(float2*)&Cout[(size_t)(row0 + 8) * ldc + col] = v1;
        }
    }
#undef LOAD_STAGE
}

// ---------------- LSTM gate epilogue ----------------
__global__ __launch_bounds__(256) void epilogue_kernel(
    int lvl,
    const int* __restrict__ indices,
    const float* __restrict__ cInit,
    float* __restrict__ outH,
    float* __restrict__ outC)
{
    int tid = threadIdx.x;
    int n = blockIdx.x * 2 + (tid >> 7);
    int d = tid & 127;

    int i0 = indices[((size_t)lvl * NN + n) * 2 + 0];
    int i1 = indices[((size_t)lvl * NN + n) * 2 + 1];
    bool L0 = (lvl == 0);

    float p0[5], p1[5];
    if (!L0 && i0 >= 0) {
        const float* rr = g_P + (size_t)i0 * NP;
#pragma unroll
        for (int w = 0; w < 5; w++) p0[w] = rr[w * 128 + d];
    } else {
#pragma unroll
        for (int w = 0; w < 5; w++) p0[w] = g_Pinit[w * 128 + d];
    }
    if (!L0 && i1 >= 0) {
        const float* rr = g_P + (size_t)i1 * NP + 640;
#pragma unroll
        for (int w = 0; w < 5; w++) p1[w] = rr[w * 128 + d];
    } else {
#pragma unroll
        for (int w = 0; w < 5; w++) p1[w] = g_Pinit[640 + w * 128 + d];
    }

    const float4 wv = *(const float4*)&g_Wx[(((size_t)lvl * NN + n) << 9) + (d << 2)];
    // wv: x=f_x, y=i_x, z=u_x, w=o_x
    float f1 = sigmoidf_(wv.x + p0[0] + p1[0]);
    float f2 = sigmoidf_(wv.x + p0[1] + p1[1]);
    float ig = sigmoidf_(wv.y + p0[2] + p1[2]);
    float ug = tanhf(wv.z + p0[3] + p1[3]);
    float og = sigmoidf_(wv.w + p0[4] + p1[4]);

    const float* prevC = outC + (size_t)(lvl - 1) * NN * DOUT;
    float cc0 = (!L0 && i0 >= 0) ? prevC[(size_t)i0 * DOUT + d] : cInit[d];
    float cc1 = (!L0 && i1 >= 0) ? prevC[(size_t)i1 * DOUT + d] : cInit[d];

    float nc = ig * ug + f1 * cc0 + f2 * cc1;
    float nh = og * tanhf(nc);

    size_t o = ((size_t)lvl * NN + n) * DOUT + d;
    outH[o] = nh;
    outC[o] = nc;

    // fp16 copy of h for the next level's tensor-core GEMM
    g_Hh[(size_t)n * DOUT + d] = __float2half(nh);
}

extern "C" void kernel_launch(void* const* d_in, const int* in_sizes, int n_in,
                              void* d_out, int out_size) {
    const float* tensor = (const float*)d_in[0];   // [L, N, DIN]
    const int*   indices = (const int*)d_in[1];    // [L, N, 2]
    const float* h_init = (const float*)d_in[2];   // [1, DOUT]
    const float* c_init = (const float*)d_in[3];   // [1, DOUT]
    const float* W_w   = (const float*)d_in[4];    // [4*DOUT, DIN]
    const float* W_b   = (const float*)d_in[5];    // [4*DOUT]
    const float* U_f1  = (const float*)d_in[6];    // [DOUT, 2*DOUT]
    const float* U_f2  = (const float*)d_in[7];
    const float* U_iuo = (const float*)d_in[8];    // [3*DOUT, 2*DOUT]

    float* outH = (float*)d_out;                         // res_h [L,N,DOUT]
    float* outC = outH + (size_t)LL * NN * DOUT;         // res_c [L,N,DOUT]

    cudaFuncSetAttribute(mma_gemm<0>, cudaFuncAttributeMaxDynamicSharedMemorySize, SM_TOT);
    cudaFuncSetAttribute(mma_gemm<1>, cudaFuncAttributeMaxDynamicSharedMemorySize, SM_TOT);

    build_ah<<<(LL * NN * DIN / 4) / 256, 256>>>(tensor);
    build_bw<<<(NWX * DIN + 255) / 256, 256>>>(W_w, W_b);
    build_upair<<<(NP * 128 + 255) / 256, 256>>>(U_f1, U_f2, U_iuo);
    build_pinit<<<(NP * 32 + 255) / 256, 256>>>(h_init);

    // pre: W_x = X @ Ww^T + b.  M = L*N, N = 512, K = 256.
    {
        dim3 g(NWX / 128, (LL * NN) / 128);              // (4, 1536)
        mma_gemm<0><<<g, 256, SM_TOT>>>();
    }

    dim3 pg(NP / 128, NN / 128);                         // (10, 64)
    for (int lvl = 0; lvl < LL; lvl++) {
        if (lvl > 0) {
            mma_gemm<1><<<pg, 256, SM_TOT>>>();
        }
        epilogue_kernel<<<NN / 2, 256>>>(lvl, indices, c_init, outH, outC);
    }
}